// round 1
// baseline (speedup 1.0000x reference)
#include <cuda_runtime.h>
#include <cuda_bf16.h>
#include <math.h>

// Problem constants
#define BB 4
#define SS 512
#define DD 512
#define HH 8
#define DKV 64
#define DFF 2048
#define LL 6
#define NTOK (BB*SS)          // 2048
#define EPS 1e-5f

// Scratch (device globals; no allocation allowed)
__device__ __align__(128) float g_h[NTOK*DD];
__device__ __align__(128) float g_q[NTOK*DD];
__device__ __align__(128) float g_k[NTOK*DD];
__device__ __align__(128) float g_v[NTOK*DD];
__device__ __align__(128) float g_ctx[NTOK*DD];
__device__ __align__(128) float g_tmp[NTOK*DD];
__device__ __align__(128) float g_ff[NTOK*DFF];

// ---------------------------------------------------------------------------
// Embedding: h[b,s,:] = emb[x[b,s],:] + pe[s,:]
// grid 2048 (token), block 128, float4 per thread
// ---------------------------------------------------------------------------
__global__ void embed_kernel(const int* __restrict__ x,
                             const float* __restrict__ emb,
                             const float* __restrict__ pe,
                             float* __restrict__ h)
{
    int tok = blockIdx.x;
    int s = tok & (SS-1);
    int id = x[tok];
    int t = threadIdx.x; // 0..127, each handles 4 floats
    const float4* e4 = reinterpret_cast<const float4*>(emb + (size_t)id*DD);
    const float4* p4 = reinterpret_cast<const float4*>(pe + (size_t)s*DD);
    float4 ev = e4[t], pv = p4[t];
    float4 r; r.x=ev.x+pv.x; r.y=ev.y+pv.y; r.z=ev.z+pv.z; r.w=ev.w+pv.w;
    reinterpret_cast<float4*>(h + (size_t)tok*DD)[t] = r;
}

// ---------------------------------------------------------------------------
// Big GEMM: C[M,N] = A[M,K] @ B[K,N] (+bias) (+residual) (opt GELU)
// tile 128x128, kstep 8, 256 threads, 8x8 per thread
// grid: (N/128, M/128)
// ---------------------------------------------------------------------------
__device__ __forceinline__ float gelu_f(float x) {
    return 0.5f * x * (1.0f + tanhf(0.7978845608028654f * (x + 0.044715f*x*x*x)));
}

__global__ __launch_bounds__(256) void gemm128(
    const float* __restrict__ A, int lda,
    const float* __restrict__ B, int ldb,
    const float* __restrict__ bias,
    const float* __restrict__ res,
    float* __restrict__ C, int ldc,
    int K, int act)
{
    __shared__ float As[8][132];
    __shared__ float Bs[8][132];
    int tid = threadIdx.x;
    int tx = tid & 15, ty = tid >> 4;
    int m0 = blockIdx.y * 128, n0 = blockIdx.x * 128;
    const float* Ab = A + (size_t)m0 * lda;
    const float* Bb = B + n0;

    float acc[8][8];
#pragma unroll
    for (int r = 0; r < 8; r++)
#pragma unroll
        for (int c = 0; c < 8; c++) acc[r][c] = 0.f;

    int la_m  = tid >> 1;          // 0..127
    int la_kk = (tid & 1) * 4;     // 0 or 4
    int lb_n  = tid & 127;
    int lb_kk = tid >> 7;          // 0 or 1

    for (int k0 = 0; k0 < K; k0 += 8) {
        // load A tile: 128 rows x 8 k, float4 along k
        float4 va = *reinterpret_cast<const float4*>(Ab + (size_t)la_m * lda + k0 + la_kk);
        As[la_kk+0][la_m] = va.x;
        As[la_kk+1][la_m] = va.y;
        As[la_kk+2][la_m] = va.z;
        As[la_kk+3][la_m] = va.w;
        // load B tile: 8 k x 128 n, coalesced
#pragma unroll
        for (int i = 0; i < 4; i++)
            Bs[lb_kk + 2*i][lb_n] = Bb[(size_t)(k0 + lb_kk + 2*i) * ldb + lb_n];
        __syncthreads();
#pragma unroll
        for (int kk = 0; kk < 8; kk++) {
            float4 a0 = *reinterpret_cast<const float4*>(&As[kk][ty*8]);
            float4 a1 = *reinterpret_cast<const float4*>(&As[kk][ty*8+4]);
            float4 b0 = *reinterpret_cast<const float4*>(&Bs[kk][tx*8]);
            float4 b1 = *reinterpret_cast<const float4*>(&Bs[kk][tx*8+4]);
            float a[8] = {a0.x,a0.y,a0.z,a0.w,a1.x,a1.y,a1.z,a1.w};
            float b[8] = {b0.x,b0.y,b0.z,b0.w,b1.x,b1.y,b1.z,b1.w};
#pragma unroll
            for (int r = 0; r < 8; r++)
#pragma unroll
                for (int c = 0; c < 8; c++)
                    acc[r][c] = fmaf(a[r], b[c], acc[r][c]);
        }
        __syncthreads();
    }

#pragma unroll
    for (int r = 0; r < 8; r++) {
        int m = m0 + ty*8 + r;
#pragma unroll
        for (int c = 0; c < 8; c++) {
            int n = n0 + tx*8 + c;
            float vv = acc[r][c];
            if (bias) vv += bias[n];
            if (res)  vv += res[(size_t)m*ldc + n];
            if (act)  vv = gelu_f(vv);
            C[(size_t)m*ldc + n] = vv;
        }
    }
}

// ---------------------------------------------------------------------------
// Scores: per (b,h): S = Q Kt^T * scale, masked; write to attn slab in d_out
// tile 64x64, kstep 16 (K=64), 256 threads, 4x4 per thread
// grid (8, 8, 32) = (n tiles, m tiles, b*H)
// ---------------------------------------------------------------------------
__global__ __launch_bounds__(256) void score_gemm(
    const float* __restrict__ Q,
    const float* __restrict__ Kt,
    const int* __restrict__ x,
    float* __restrict__ attn, int l, float scale)
{
    __shared__ float As[64][17];
    __shared__ float Bs[16][65];
    int tid = threadIdx.x;
    int tx = tid & 15, ty = tid >> 4;
    int z = blockIdx.z;
    int b = z >> 3, hh = z & 7;
    int m0 = blockIdx.y * 64, n0 = blockIdx.x * 64;
    const float* Aq = Q  + (size_t)b*SS*DD + hh*DKV;
    const float* Bk = Kt + (size_t)b*SS*DD + hh*DKV;
    float* out = attn + (((size_t)b*LL + l)*HH + hh) * (size_t)(SS*SS);

    float acc[4][4];
#pragma unroll
    for (int r=0;r<4;r++)
#pragma unroll
        for (int c=0;c<4;c++) acc[r][c]=0.f;

    int lm = tid >> 4;   // 0..15 (+16*i)
    int lk = tid & 15;

#pragma unroll
    for (int k0 = 0; k0 < DKV; k0 += 16) {
#pragma unroll
        for (int i = 0; i < 4; i++) {
            int m = lm + 16*i;
            As[m][lk] = Aq[(size_t)(m0+m)*DD + k0 + lk];
            Bs[lk][m] = Bk[(size_t)(n0+m)*DD + k0 + lk];
        }
        __syncthreads();
#pragma unroll
        for (int kk = 0; kk < 16; kk++) {
            float a[4], bfr[4];
#pragma unroll
            for (int r=0;r<4;r++) a[r]   = As[ty*4+r][kk];
#pragma unroll
            for (int c=0;c<4;c++) bfr[c] = Bs[kk][tx*4+c];
#pragma unroll
            for (int r=0;r<4;r++)
#pragma unroll
                for (int c=0;c<4;c++) acc[r][c] = fmaf(a[r], bfr[c], acc[r][c]);
        }
        __syncthreads();
    }

#pragma unroll
    for (int c = 0; c < 4; c++) {
        int n = n0 + tx*4 + c;
        bool masked = (x[b*SS + n] == 0);
#pragma unroll
        for (int r = 0; r < 4; r++) {
            int m = m0 + ty*4 + r;
            float vv = masked ? -1e9f : acc[r][c] * scale;
            out[(size_t)m*SS + n] = vv;
        }
    }
}

// ---------------------------------------------------------------------------
// Softmax in-place over rows of 512 in attn slab for layer l
// grid B*H*S = 16384, block 128 (4 elems/thread)
// ---------------------------------------------------------------------------
__global__ __launch_bounds__(128) void softmax_kernel(float* __restrict__ attn, int l)
{
    __shared__ float red[8];
    int row = blockIdx.x;
    int b = row >> 12;          // / (H*S)
    int rem = row & 4095;
    float* p = attn + (size_t)b*(LL*HH*SS*SS) + (size_t)l*(HH*SS*SS) + (size_t)rem*SS;
    int t = threadIdx.x;
    int lane = t & 31, wid = t >> 5;

    float v[4];
#pragma unroll
    for (int i = 0; i < 4; i++) v[i] = p[t + 128*i];

    float mx = fmaxf(fmaxf(v[0],v[1]), fmaxf(v[2],v[3]));
#pragma unroll
    for (int o = 16; o > 0; o >>= 1) mx = fmaxf(mx, __shfl_xor_sync(0xffffffffu, mx, o));
    if (lane == 0) red[wid] = mx;
    __syncthreads();
    mx = fmaxf(fmaxf(red[0],red[1]), fmaxf(red[2],red[3]));

    float s = 0.f;
#pragma unroll
    for (int i = 0; i < 4; i++) { v[i] = __expf(v[i] - mx); s += v[i]; }
#pragma unroll
    for (int o = 16; o > 0; o >>= 1) s += __shfl_xor_sync(0xffffffffu, s, o);
    if (lane == 0) red[4 + wid] = s;
    __syncthreads();
    s = red[4] + red[5] + red[6] + red[7];
    float inv = 1.0f / s;
#pragma unroll
    for (int i = 0; i < 4; i++) p[t + 128*i] = v[i] * inv;
}

// ---------------------------------------------------------------------------
// ctx = attn @ V  per (b,h): M=512, N=64, K=512
// tile 64x64, kstep 16, 256 threads, 4x4 per thread
// grid (8 m tiles, 32 z)
// ---------------------------------------------------------------------------
__global__ __launch_bounds__(256) void ctx_gemm(
    const float* __restrict__ attn,
    const float* __restrict__ V,
    float* __restrict__ C, int l)
{
    __shared__ float As[64][17];
    __shared__ float Bs[16][65];
    int tid = threadIdx.x;
    int tx = tid & 15, ty = tid >> 4;
    int z = blockIdx.y;
    int b = z >> 3, hh = z & 7;
    int m0 = blockIdx.x * 64;
    const float* A  = attn + (((size_t)b*LL + l)*HH + hh) * (size_t)(SS*SS);
    const float* Bb = V + (size_t)b*SS*DD + hh*DKV;
    float* Cb = C + (size_t)b*SS*DD + hh*DKV;

    float acc[4][4];
#pragma unroll
    for (int r=0;r<4;r++)
#pragma unroll
        for (int c=0;c<4;c++) acc[r][c]=0.f;

    int lam = tid >> 4, lak = tid & 15;      // A loader
    int lbn = tid & 63, lbk = tid >> 6;      // B loader (0..3)

    for (int k0 = 0; k0 < SS; k0 += 16) {
#pragma unroll
        for (int i = 0; i < 4; i++) {
            int m = lam + 16*i;
            As[m][lak] = A[(size_t)(m0+m)*SS + k0 + lak];
            Bs[lbk + 4*i][lbn] = Bb[(size_t)(k0 + lbk + 4*i)*DD + lbn];
        }
        __syncthreads();
#pragma unroll
        for (int kk = 0; kk < 16; kk++) {
            float a[4], bfr[4];
#pragma unroll
            for (int r=0;r<4;r++) a[r]   = As[ty*4+r][kk];
#pragma unroll
            for (int c=0;c<4;c++) bfr[c] = Bs[kk][tx*4+c];
#pragma unroll
            for (int r=0;r<4;r++)
#pragma unroll
                for (int c=0;c<4;c++) acc[r][c] = fmaf(a[r], bfr[c], acc[r][c]);
        }
        __syncthreads();
    }

#pragma unroll
    for (int r = 0; r < 4; r++) {
        int m = m0 + ty*4 + r;
#pragma unroll
        for (int c = 0; c < 4; c++) {
            int n = tx*4 + c;
            Cb[(size_t)m*DD + n] = acc[r][c];
        }
    }
}

// ---------------------------------------------------------------------------
// LayerNorm: out = (x-mu)*rsqrt(var+eps)*g + b over rows of 512
// grid 2048, block 128, 4 elems/thread
// ---------------------------------------------------------------------------
__global__ __launch_bounds__(128) void ln_kernel(
    const float* __restrict__ in,
    const float* __restrict__ g,
    const float* __restrict__ bta,
    float* __restrict__ out)
{
    __shared__ float red[8];
    int row = blockIdx.x;
    const float* p = in + (size_t)row*DD;
    float* o = out + (size_t)row*DD;
    int t = threadIdx.x;
    int lane = t & 31, wid = t >> 5;

    float v[4];
    float s = 0.f, sq = 0.f;
#pragma unroll
    for (int i = 0; i < 4; i++) { v[i] = p[t + 128*i]; s += v[i]; sq += v[i]*v[i]; }
#pragma unroll
    for (int o2 = 16; o2 > 0; o2 >>= 1) {
        s  += __shfl_xor_sync(0xffffffffu, s,  o2);
        sq += __shfl_xor_sync(0xffffffffu, sq, o2);
    }
    if (lane == 0) { red[wid] = s; red[4+wid] = sq; }
    __syncthreads();
    s  = red[0]+red[1]+red[2]+red[3];
    sq = red[4]+red[5]+red[6]+red[7];
    float mu = s * (1.0f/DD);
    float var = sq * (1.0f/DD) - mu*mu;
    float rstd = rsqrtf(var + EPS);
#pragma unroll
    for (int i = 0; i < 4; i++) {
        int col = t + 128*i;
        o[col] = (v[i] - mu) * rstd * g[col] + bta[col];
    }
}

// copy g_h -> d_out head
__global__ void copy_kernel(const float* __restrict__ src, float* __restrict__ dst)
{
    int i = blockIdx.x * 128 + threadIdx.x;
    reinterpret_cast<float4*>(dst)[i] = reinterpret_cast<const float4*>(src)[i];
}

// ---------------------------------------------------------------------------
extern "C" void kernel_launch(void* const* d_in, const int* in_sizes, int n_in,
                              void* d_out, int out_size)
{
    const int*   x    = (const int*)  d_in[0];
    const float* emb  = (const float*)d_in[1];
    const float* pe   = (const float*)d_in[2];
    const float* WQ   = (const float*)d_in[3];
    const float* bQ   = (const float*)d_in[4];
    const float* WK   = (const float*)d_in[5];
    const float* bK   = (const float*)d_in[6];
    const float* WV   = (const float*)d_in[7];
    const float* bV   = (const float*)d_in[8];
    const float* WO   = (const float*)d_in[9];
    const float* bO   = (const float*)d_in[10];
    const float* ln1g = (const float*)d_in[11];
    const float* ln1b = (const float*)d_in[12];
    const float* W1   = (const float*)d_in[13];
    const float* b1   = (const float*)d_in[14];
    const float* W2   = (const float*)d_in[15];
    const float* b2   = (const float*)d_in[16];
    const float* ln2g = (const float*)d_in[17];
    const float* ln2b = (const float*)d_in[18];

    float* out  = (float*)d_out;
    float* attn = out + (size_t)NTOK*DD;   // h first, then attns [B,L,H,S,S]

    float *h, *q, *k, *v, *ctx, *tmp, *ff;
    cudaGetSymbolAddress((void**)&h,   g_h);
    cudaGetSymbolAddress((void**)&q,   g_q);
    cudaGetSymbolAddress((void**)&k,   g_k);
    cudaGetSymbolAddress((void**)&v,   g_v);
    cudaGetSymbolAddress((void**)&ctx, g_ctx);
    cudaGetSymbolAddress((void**)&tmp, g_tmp);
    cudaGetSymbolAddress((void**)&ff,  g_ff);

    const float scale = 0.125f; // 1/sqrt(64)

    embed_kernel<<<NTOK, 128>>>(x, emb, pe, h);

    for (int l = 0; l < LL; l++) {
        const float* wq = WQ + (size_t)l*DD*DD;
        const float* wk = WK + (size_t)l*DD*DD;
        const float* wv = WV + (size_t)l*DD*DD;
        const float* wo = WO + (size_t)l*DD*DD;
        const float* w1 = W1 + (size_t)l*DD*DFF;
        const float* w2 = W2 + (size_t)l*DFF*DD;

        gemm128<<<dim3(4,16), 256>>>(h, DD, wq, DD, bQ + l*DD, nullptr, q, DD, DD, 0);
        gemm128<<<dim3(4,16), 256>>>(h, DD, wk, DD, bK + l*DD, nullptr, k, DD, DD, 0);
        gemm128<<<dim3(4,16), 256>>>(h, DD, wv, DD, bV + l*DD, nullptr, v, DD, DD, 0);

        score_gemm<<<dim3(8,8,32), 256>>>(q, k, x, attn, l, scale);
        softmax_kernel<<<BB*HH*SS, 128>>>(attn, l);
        ctx_gemm<<<dim3(8,32), 256>>>(attn, v, ctx, l);

        gemm128<<<dim3(4,16), 256>>>(ctx, DD, wo, DD, bO + l*DD, h, tmp, DD, DD, 0);
        ln_kernel<<<NTOK, 128>>>(tmp, ln1g + l*DD, ln1b + l*DD, h);

        gemm128<<<dim3(16,16), 256>>>(h, DD, w1, DFF, b1 + l*DFF, nullptr, ff, DFF, DD, 1);
        gemm128<<<dim3(4,16), 256>>>(ff, DFF, w2, DD, b2 + l*DD, h, tmp, DD, DFF, 0);
        ln_kernel<<<NTOK, 128>>>(tmp, ln2g + l*DD, ln2b + l*DD, h);
    }

    copy_kernel<<<NTOK, 128>>>(h, out);
}

// round 2
// speedup vs baseline: 1.6443x; 1.6443x over previous
#include <cuda_runtime.h>
#include <cuda_bf16.h>
#include <math.h>

// Problem constants
#define BB 4
#define SS 512
#define DD 512
#define HH 8
#define DKV 64
#define DFF 2048
#define LL 6
#define NTOK (BB*SS)          // 2048
#define EPS 1e-5f

// Scratch (device globals; no allocation allowed)
__device__ __align__(128) float g_h[NTOK*DD];
__device__ __align__(128) float g_q[NTOK*DD];
__device__ __align__(128) float g_k[NTOK*DD];
__device__ __align__(128) float g_v[NTOK*DD];
__device__ __align__(128) float g_ctx[NTOK*DD];
__device__ __align__(128) float g_tmp[NTOK*DD];
__device__ __align__(128) float g_ff[NTOK*DFF];

// ---------------------------------------------------------------------------
// Embedding: h[b,s,:] = emb[x[b,s],:] + pe[s,:]
// ---------------------------------------------------------------------------
__global__ void embed_kernel(const int* __restrict__ x,
                             const float* __restrict__ emb,
                             const float* __restrict__ pe,
                             float* __restrict__ h)
{
    int tok = blockIdx.x;
    int s = tok & (SS-1);
    int id = x[tok];
    int t = threadIdx.x; // 0..127
    const float4* e4 = reinterpret_cast<const float4*>(emb + (size_t)id*DD);
    const float4* p4 = reinterpret_cast<const float4*>(pe + (size_t)s*DD);
    float4 ev = e4[t], pv = p4[t];
    float4 r; r.x=ev.x+pv.x; r.y=ev.y+pv.y; r.z=ev.z+pv.z; r.w=ev.w+pv.w;
    reinterpret_cast<float4*>(h + (size_t)tok*DD)[t] = r;
}

__device__ __forceinline__ float gelu_f(float x) {
    return 0.5f * x * (1.0f + tanhf(0.7978845608028654f * (x + 0.044715f*x*x*x)));
}

// ---------------------------------------------------------------------------
// GEMM: C[M,N] = A[M,K] @ B[K,N] (+bias) (+residual) (opt GELU)
// tile 64(M) x 128(N), kstep 16, 128 threads, 8x8 per thread,
// double-buffered smem, register-staged global loads (1 sync per k-iter)
// grid: (N/128, M/64)
// ---------------------------------------------------------------------------
__global__ __launch_bounds__(128) void gemm64x128(
    const float* __restrict__ A, int lda,
    const float* __restrict__ B, int ldb,
    const float* __restrict__ bias,
    const float* __restrict__ res,
    float* __restrict__ C, int ldc,
    int K, int act)
{
    __shared__ float As[2][16][68];
    __shared__ float Bs[2][16][132];

    int tid = threadIdx.x;
    int tx = tid & 15;        // n-group 0..15
    int ty = tid >> 4;        // m-group 0..7
    int m0 = blockIdx.y * 64, n0 = blockIdx.x * 128;

    // A loader: 64 rows x 16 k; 2 threads per row, 8 k each (2 float4)
    int m_a = tid >> 1;
    int k_a = (tid & 1) * 8;
    // B loader: 16 rows x 128 n; 8 threads per row, 16 n each (4 float4)
    int k_b = tid >> 3;
    int n_b = (tid & 7) * 16;

    const float* Aptr = A + (size_t)(m0 + m_a) * lda + k_a;
    const float* Bptr = B + (size_t)k_b * ldb + n0 + n_b;

    float acc[8][8];
#pragma unroll
    for (int r = 0; r < 8; r++)
#pragma unroll
        for (int c = 0; c < 8; c++) acc[r][c] = 0.f;

    float4 va0, va1, vb0, vb1, vb2, vb3;

    // prologue: load tile 0 -> regs -> smem buf 0
    va0 = *reinterpret_cast<const float4*>(Aptr);
    va1 = *reinterpret_cast<const float4*>(Aptr + 4);
    vb0 = *reinterpret_cast<const float4*>(Bptr);
    vb1 = *reinterpret_cast<const float4*>(Bptr + 4);
    vb2 = *reinterpret_cast<const float4*>(Bptr + 8);
    vb3 = *reinterpret_cast<const float4*>(Bptr + 12);

    As[0][k_a+0][m_a] = va0.x; As[0][k_a+1][m_a] = va0.y;
    As[0][k_a+2][m_a] = va0.z; As[0][k_a+3][m_a] = va0.w;
    As[0][k_a+4][m_a] = va1.x; As[0][k_a+5][m_a] = va1.y;
    As[0][k_a+6][m_a] = va1.z; As[0][k_a+7][m_a] = va1.w;
    *reinterpret_cast<float4*>(&Bs[0][k_b][n_b+ 0]) = vb0;
    *reinterpret_cast<float4*>(&Bs[0][k_b][n_b+ 4]) = vb1;
    *reinterpret_cast<float4*>(&Bs[0][k_b][n_b+ 8]) = vb2;
    *reinterpret_cast<float4*>(&Bs[0][k_b][n_b+12]) = vb3;
    __syncthreads();

    int nk = K >> 4;
    for (int it = 0; it < nk; it++) {
        int cur = it & 1;
        bool has_next = (it + 1 < nk);
        if (has_next) {
            const float* Ap = Aptr + (it + 1) * 16;
            const float* Bp = Bptr + (size_t)(it + 1) * 16 * ldb;
            va0 = *reinterpret_cast<const float4*>(Ap);
            va1 = *reinterpret_cast<const float4*>(Ap + 4);
            vb0 = *reinterpret_cast<const float4*>(Bp);
            vb1 = *reinterpret_cast<const float4*>(Bp + 4);
            vb2 = *reinterpret_cast<const float4*>(Bp + 8);
            vb3 = *reinterpret_cast<const float4*>(Bp + 12);
        }
#pragma unroll
        for (int kk = 0; kk < 16; kk++) {
            float4 a0 = *reinterpret_cast<const float4*>(&As[cur][kk][ty*8]);
            float4 a1 = *reinterpret_cast<const float4*>(&As[cur][kk][ty*8+4]);
            float4 b0 = *reinterpret_cast<const float4*>(&Bs[cur][kk][tx*4]);
            float4 b1 = *reinterpret_cast<const float4*>(&Bs[cur][kk][64+tx*4]);
            float a[8] = {a0.x,a0.y,a0.z,a0.w,a1.x,a1.y,a1.z,a1.w};
            float b[8] = {b0.x,b0.y,b0.z,b0.w,b1.x,b1.y,b1.z,b1.w};
#pragma unroll
            for (int r = 0; r < 8; r++)
#pragma unroll
                for (int c = 0; c < 8; c++)
                    acc[r][c] = fmaf(a[r], b[c], acc[r][c]);
        }
        if (has_next) {
            int nb = cur ^ 1;
            As[nb][k_a+0][m_a] = va0.x; As[nb][k_a+1][m_a] = va0.y;
            As[nb][k_a+2][m_a] = va0.z; As[nb][k_a+3][m_a] = va0.w;
            As[nb][k_a+4][m_a] = va1.x; As[nb][k_a+5][m_a] = va1.y;
            As[nb][k_a+6][m_a] = va1.z; As[nb][k_a+7][m_a] = va1.w;
            *reinterpret_cast<float4*>(&Bs[nb][k_b][n_b+ 0]) = vb0;
            *reinterpret_cast<float4*>(&Bs[nb][k_b][n_b+ 4]) = vb1;
            *reinterpret_cast<float4*>(&Bs[nb][k_b][n_b+ 8]) = vb2;
            *reinterpret_cast<float4*>(&Bs[nb][k_b][n_b+12]) = vb3;
        }
        __syncthreads();
    }

    // epilogue
    float4 bias0, bias1;
    if (bias) {
        bias0 = *reinterpret_cast<const float4*>(&bias[n0 + tx*4]);
        bias1 = *reinterpret_cast<const float4*>(&bias[n0 + 64 + tx*4]);
    } else {
        bias0 = make_float4(0.f,0.f,0.f,0.f);
        bias1 = bias0;
    }
#pragma unroll
    for (int r = 0; r < 8; r++) {
        int m = m0 + ty*8 + r;
        float* Crow = C + (size_t)m * ldc + n0;
        float4 o0, o1;
        o0.x = acc[r][0] + bias0.x; o0.y = acc[r][1] + bias0.y;
        o0.z = acc[r][2] + bias0.z; o0.w = acc[r][3] + bias0.w;
        o1.x = acc[r][4] + bias1.x; o1.y = acc[r][5] + bias1.y;
        o1.z = acc[r][6] + bias1.z; o1.w = acc[r][7] + bias1.w;
        if (res) {
            const float* Rrow = res + (size_t)m * ldc + n0;
            float4 r0 = *reinterpret_cast<const float4*>(&Rrow[tx*4]);
            float4 r1 = *reinterpret_cast<const float4*>(&Rrow[64 + tx*4]);
            o0.x += r0.x; o0.y += r0.y; o0.z += r0.z; o0.w += r0.w;
            o1.x += r1.x; o1.y += r1.y; o1.z += r1.z; o1.w += r1.w;
        }
        if (act) {
            o0.x = gelu_f(o0.x); o0.y = gelu_f(o0.y);
            o0.z = gelu_f(o0.z); o0.w = gelu_f(o0.w);
            o1.x = gelu_f(o1.x); o1.y = gelu_f(o1.y);
            o1.z = gelu_f(o1.z); o1.w = gelu_f(o1.w);
        }
        *reinterpret_cast<float4*>(&Crow[tx*4])      = o0;
        *reinterpret_cast<float4*>(&Crow[64 + tx*4]) = o1;
    }
}

// ---------------------------------------------------------------------------
// Scores: per (b,h): S = Q K^T * scale, masked; write to attn slab in d_out
// tile 64x64, kstep 16 (K=64), 256 threads, 4x4 per thread
// grid (8, 8, 32)
// ---------------------------------------------------------------------------
__global__ __launch_bounds__(256) void score_gemm(
    const float* __restrict__ Q,
    const float* __restrict__ Kt,
    const int* __restrict__ x,
    float* __restrict__ attn, int l, float scale)
{
    __shared__ float As[64][17];
    __shared__ float Bs[16][65];
    int tid = threadIdx.x;
    int tx = tid & 15, ty = tid >> 4;
    int z = blockIdx.z;
    int b = z >> 3, hh = z & 7;
    int m0 = blockIdx.y * 64, n0 = blockIdx.x * 64;
    const float* Aq = Q  + (size_t)b*SS*DD + hh*DKV;
    const float* Bk = Kt + (size_t)b*SS*DD + hh*DKV;
    float* out = attn + (((size_t)b*LL + l)*HH + hh) * (size_t)(SS*SS);

    float acc[4][4];
#pragma unroll
    for (int r=0;r<4;r++)
#pragma unroll
        for (int c=0;c<4;c++) acc[r][c]=0.f;

    int lm = tid >> 4;
    int lk = tid & 15;

#pragma unroll
    for (int k0 = 0; k0 < DKV; k0 += 16) {
#pragma unroll
        for (int i = 0; i < 4; i++) {
            int m = lm + 16*i;
            As[m][lk] = Aq[(size_t)(m0+m)*DD + k0 + lk];
            Bs[lk][m] = Bk[(size_t)(n0+m)*DD + k0 + lk];
        }
        __syncthreads();
#pragma unroll
        for (int kk = 0; kk < 16; kk++) {
            float a[4], bfr[4];
#pragma unroll
            for (int r=0;r<4;r++) a[r]   = As[ty*4+r][kk];
#pragma unroll
            for (int c=0;c<4;c++) bfr[c] = Bs[kk][tx*4+c];
#pragma unroll
            for (int r=0;r<4;r++)
#pragma unroll
                for (int c=0;c<4;c++) acc[r][c] = fmaf(a[r], bfr[c], acc[r][c]);
        }
        __syncthreads();
    }

#pragma unroll
    for (int c = 0; c < 4; c++) {
        int n = n0 + tx*4 + c;
        bool masked = (x[b*SS + n] == 0);
#pragma unroll
        for (int r = 0; r < 4; r++) {
            int m = m0 + ty*4 + r;
            float vv = masked ? -1e9f : acc[r][c] * scale;
            out[(size_t)m*SS + n] = vv;
        }
    }
}

// ---------------------------------------------------------------------------
// Softmax in-place over rows of 512 in attn slab for layer l
// ---------------------------------------------------------------------------
__global__ __launch_bounds__(128) void softmax_kernel(float* __restrict__ attn, int l)
{
    __shared__ float red[8];
    int row = blockIdx.x;
    int b = row >> 12;
    int rem = row & 4095;
    float* p = attn + (size_t)b*(LL*HH*SS*SS) + (size_t)l*(HH*SS*SS) + (size_t)rem*SS;
    int t = threadIdx.x;
    int lane = t & 31, wid = t >> 5;

    float v[4];
#pragma unroll
    for (int i = 0; i < 4; i++) v[i] = p[t + 128*i];

    float mx = fmaxf(fmaxf(v[0],v[1]), fmaxf(v[2],v[3]));
#pragma unroll
    for (int o = 16; o > 0; o >>= 1) mx = fmaxf(mx, __shfl_xor_sync(0xffffffffu, mx, o));
    if (lane == 0) red[wid] = mx;
    __syncthreads();
    mx = fmaxf(fmaxf(red[0],red[1]), fmaxf(red[2],red[3]));

    float s = 0.f;
#pragma unroll
    for (int i = 0; i < 4; i++) { v[i] = __expf(v[i] - mx); s += v[i]; }
#pragma unroll
    for (int o = 16; o > 0; o >>= 1) s += __shfl_xor_sync(0xffffffffu, s, o);
    if (lane == 0) red[4 + wid] = s;
    __syncthreads();
    s = red[4] + red[5] + red[6] + red[7];
    float inv = 1.0f / s;
#pragma unroll
    for (int i = 0; i < 4; i++) p[t + 128*i] = v[i] * inv;
}

// ---------------------------------------------------------------------------
// ctx = attn @ V  per (b,h): M=512, N=64, K=512
// ---------------------------------------------------------------------------
__global__ __launch_bounds__(256) void ctx_gemm(
    const float* __restrict__ attn,
    const float* __restrict__ V,
    float* __restrict__ C, int l)
{
    __shared__ float As[64][17];
    __shared__ float Bs[16][65];
    int tid = threadIdx.x;
    int tx = tid & 15, ty = tid >> 4;
    int z = blockIdx.y;
    int b = z >> 3, hh = z & 7;
    int m0 = blockIdx.x * 64;
    const float* A  = attn + (((size_t)b*LL + l)*HH + hh) * (size_t)(SS*SS);
    const float* Bb = V + (size_t)b*SS*DD + hh*DKV;
    float* Cb = C + (size_t)b*SS*DD + hh*DKV;

    float acc[4][4];
#pragma unroll
    for (int r=0;r<4;r++)
#pragma unroll
        for (int c=0;c<4;c++) acc[r][c]=0.f;

    int lam = tid >> 4, lak = tid & 15;
    int lbn = tid & 63, lbk = tid >> 6;

    for (int k0 = 0; k0 < SS; k0 += 16) {
#pragma unroll
        for (int i = 0; i < 4; i++) {
            int m = lam + 16*i;
            As[m][lak] = A[(size_t)(m0+m)*SS + k0 + lak];
            Bs[lbk + 4*i][lbn] = Bb[(size_t)(k0 + lbk + 4*i)*DD + lbn];
        }
        __syncthreads();
#pragma unroll
        for (int kk = 0; kk < 16; kk++) {
            float a[4], bfr[4];
#pragma unroll
            for (int r=0;r<4;r++) a[r]   = As[ty*4+r][kk];
#pragma unroll
            for (int c=0;c<4;c++) bfr[c] = Bs[kk][tx*4+c];
#pragma unroll
            for (int r=0;r<4;r++)
#pragma unroll
                for (int c=0;c<4;c++) acc[r][c] = fmaf(a[r], bfr[c], acc[r][c]);
        }
        __syncthreads();
    }

#pragma unroll
    for (int r = 0; r < 4; r++) {
        int m = m0 + ty*4 + r;
#pragma unroll
        for (int c = 0; c < 4; c++) {
            int n = tx*4 + c;
            Cb[(size_t)m*DD + n] = acc[r][c];
        }
    }
}

// ---------------------------------------------------------------------------
// LayerNorm
// ---------------------------------------------------------------------------
__global__ __launch_bounds__(128) void ln_kernel(
    const float* __restrict__ in,
    const float* __restrict__ g,
    const float* __restrict__ bta,
    float* __restrict__ out)
{
    __shared__ float red[8];
    int row = blockIdx.x;
    const float* p = in + (size_t)row*DD;
    float* o = out + (size_t)row*DD;
    int t = threadIdx.x;
    int lane = t & 31, wid = t >> 5;

    float v[4];
    float s = 0.f, sq = 0.f;
#pragma unroll
    for (int i = 0; i < 4; i++) { v[i] = p[t + 128*i]; s += v[i]; sq += v[i]*v[i]; }
#pragma unroll
    for (int o2 = 16; o2 > 0; o2 >>= 1) {
        s  += __shfl_xor_sync(0xffffffffu, s,  o2);
        sq += __shfl_xor_sync(0xffffffffu, sq, o2);
    }
    if (lane == 0) { red[wid] = s; red[4+wid] = sq; }
    __syncthreads();
    s  = red[0]+red[1]+red[2]+red[3];
    sq = red[4]+red[5]+red[6]+red[7];
    float mu = s * (1.0f/DD);
    float var = sq * (1.0f/DD) - mu*mu;
    float rstd = rsqrtf(var + EPS);
#pragma unroll
    for (int i = 0; i < 4; i++) {
        int col = t + 128*i;
        o[col] = (v[i] - mu) * rstd * g[col] + bta[col];
    }
}

// ---------------------------------------------------------------------------
extern "C" void kernel_launch(void* const* d_in, const int* in_sizes, int n_in,
                              void* d_out, int out_size)
{
    const int*   x    = (const int*)  d_in[0];
    const float* emb  = (const float*)d_in[1];
    const float* pe   = (const float*)d_in[2];
    const float* WQ   = (const float*)d_in[3];
    const float* bQ   = (const float*)d_in[4];
    const float* WK   = (const float*)d_in[5];
    const float* bK   = (const float*)d_in[6];
    const float* WV   = (const float*)d_in[7];
    const float* bV   = (const float*)d_in[8];
    const float* WO   = (const float*)d_in[9];
    const float* bO   = (const float*)d_in[10];
    const float* ln1g = (const float*)d_in[11];
    const float* ln1b = (const float*)d_in[12];
    const float* W1   = (const float*)d_in[13];
    const float* b1   = (const float*)d_in[14];
    const float* W2   = (const float*)d_in[15];
    const float* b2   = (const float*)d_in[16];
    const float* ln2g = (const float*)d_in[17];
    const float* ln2b = (const float*)d_in[18];

    float* out  = (float*)d_out;
    float* attn = out + (size_t)NTOK*DD;   // h first, then attns [B,L,H,S,S]

    float *h, *q, *k, *v, *ctx, *tmp, *ff;
    cudaGetSymbolAddress((void**)&h,   g_h);
    cudaGetSymbolAddress((void**)&q,   g_q);
    cudaGetSymbolAddress((void**)&k,   g_k);
    cudaGetSymbolAddress((void**)&v,   g_v);
    cudaGetSymbolAddress((void**)&ctx, g_ctx);
    cudaGetSymbolAddress((void**)&tmp, g_tmp);
    cudaGetSymbolAddress((void**)&ff,  g_ff);

    const float scale = 0.125f; // 1/sqrt(64)

    embed_kernel<<<NTOK, 128>>>(x, emb, pe, h);

    for (int l = 0; l < LL; l++) {
        const float* wq = WQ + (size_t)l*DD*DD;
        const float* wk = WK + (size_t)l*DD*DD;
        const float* wv = WV + (size_t)l*DD*DD;
        const float* wo = WO + (size_t)l*DD*DD;
        const float* w1 = W1 + (size_t)l*DD*DFF;
        const float* w2 = W2 + (size_t)l*DFF*DD;

        gemm64x128<<<dim3(4,32), 128>>>(h, DD, wq, DD, bQ + l*DD, nullptr, q, DD, DD, 0);
        gemm64x128<<<dim3(4,32), 128>>>(h, DD, wk, DD, bK + l*DD, nullptr, k, DD, DD, 0);
        gemm64x128<<<dim3(4,32), 128>>>(h, DD, wv, DD, bV + l*DD, nullptr, v, DD, DD, 0);

        score_gemm<<<dim3(8,8,32), 256>>>(q, k, x, attn, l, scale);
        softmax_kernel<<<BB*HH*SS, 128>>>(attn, l);
        ctx_gemm<<<dim3(8,32), 256>>>(attn, v, ctx, l);

        gemm64x128<<<dim3(4,32), 128>>>(ctx, DD, wo, DD, bO + l*DD, h, tmp, DD, DD, 0);
        ln_kernel<<<NTOK, 128>>>(tmp, ln1g + l*DD, ln1b + l*DD, h);

        gemm64x128<<<dim3(16,32), 128>>>(h, DD, w1, DFF, b1 + l*DFF, nullptr, ff, DFF, DD, 1);
        gemm64x128<<<dim3(4,32), 128>>>(ff, DFF, w2, DD, b2 + l*DD, h, tmp, DD, DFF, 0);

        float* lnout = (l == LL-1) ? out : h;
        ln_kernel<<<NTOK, 128>>>(tmp, ln2g + l*DD, ln2b + l*DD, lnout);
    }
}

// round 3
// speedup vs baseline: 2.4597x; 1.4959x over previous
#include <cuda_runtime.h>
#include <cuda_bf16.h>
#include <math.h>
#include <stdint.h>

// Problem constants
#define BB 4
#define SS 512
#define DD 512
#define HH 8
#define DKV 64
#define DFF 2048
#define LL 6
#define NTOK (BB*SS)          // 2048
#define EPS 1e-5f

// Scratch (device globals; no allocation allowed)
__device__ __align__(128) float g_h[NTOK*DD];
__device__ __align__(128) float g_q[NTOK*DD];
__device__ __align__(128) float g_k[NTOK*DD];
__device__ __align__(128) float g_v[NTOK*DD];
__device__ __align__(128) float g_ctx[NTOK*DD];
__device__ __align__(128) float g_tmp[NTOK*DD];
__device__ __align__(128) float g_ff[NTOK*DFF];

// ---------------------------------------------------------------------------
__global__ void embed_kernel(const int* __restrict__ x,
                             const float* __restrict__ emb,
                             const float* __restrict__ pe,
                             float* __restrict__ h)
{
    int tok = blockIdx.x;
    int s = tok & (SS-1);
    int id = x[tok];
    int t = threadIdx.x; // 0..127
    const float4* e4 = reinterpret_cast<const float4*>(emb + (size_t)id*DD);
    const float4* p4 = reinterpret_cast<const float4*>(pe + (size_t)s*DD);
    float4 ev = e4[t], pv = p4[t];
    float4 r; r.x=ev.x+pv.x; r.y=ev.y+pv.y; r.z=ev.z+pv.z; r.w=ev.w+pv.w;
    reinterpret_cast<float4*>(h + (size_t)tok*DD)[t] = r;
}

__device__ __forceinline__ float gelu_f(float x) {
    return 0.5f * x * (1.0f + tanhf(0.7978845608028654f * (x + 0.044715f*x*x*x)));
}

__device__ __forceinline__ float tf32_of(float x) {
    uint32_t u;
    asm("cvt.rna.tf32.f32 %0, %1;" : "=r"(u) : "f"(x));
    return __uint_as_float(u);
}

__device__ __forceinline__ void mma_tf32(float* c, const uint32_t* a, const uint32_t* b) {
    asm volatile(
        "mma.sync.aligned.m16n8k8.row.col.f32.tf32.tf32.f32 "
        "{%0,%1,%2,%3}, {%4,%5,%6,%7}, {%8,%9}, {%0,%1,%2,%3};"
        : "+f"(c[0]), "+f"(c[1]), "+f"(c[2]), "+f"(c[3])
        : "r"(a[0]), "r"(a[1]), "r"(a[2]), "r"(a[3]), "r"(b[0]), "r"(b[1]));
}

// ---------------------------------------------------------------------------
// TF32 tensor-core GEMM: C[M,N] = A[M,K] @ B[K,N] (+bias)(+res)(+gelu)
// CTA tile 128(M) x 64(N), BK=16, 256 threads (8 warps: 4m x 2n, 32x32 warp).
// Per warp: 2 m16-tiles x 4 n8-tiles of m16n8k8 mma.
// blockIdx.z selects among up to 3 (B, bias, C) triples (QKV fusion).
// grid: (N/64, M/128, nz)
// ---------------------------------------------------------------------------
__global__ __launch_bounds__(256) void gemm_tf32(
    const float* __restrict__ A, int lda,
    const float* __restrict__ B0, const float* __restrict__ B1, const float* __restrict__ B2,
    int ldb,
    const float* __restrict__ bias0, const float* __restrict__ bias1, const float* __restrict__ bias2,
    const float* __restrict__ res,
    float* __restrict__ C0, float* __restrict__ C1, float* __restrict__ C2,
    int ldc, int K, int act)
{
    int z = blockIdx.z;
    const float* B    = (z == 0) ? B0    : ((z == 1) ? B1    : B2);
    const float* bias = (z == 0) ? bias0 : ((z == 1) ? bias1 : bias2);
    float*       C    = (z == 0) ? C0    : ((z == 1) ? C1    : C2);

    __shared__ float As[2][16][136];   // [k][m], pad 8 -> (8k+m)%32 conflict-free frag loads
    __shared__ float Bs[2][16][72];    // [k][n], pad 8

    int tid  = threadIdx.x;
    int lane = tid & 31, warp = tid >> 5;
    int g    = lane >> 2, tig = lane & 3;
    int wm   = (warp & 3) * 32;        // 4 m-warps
    int wn   = (warp >> 2) * 32;       // 2 n-warps
    int m0   = blockIdx.y * 128, n0 = blockIdx.x * 64;

    // loaders
    int am = tid & 127;                // A row
    int aq = (tid >> 7) * 4;           // A col group {0,4}
    int bn = (tid & 15) * 4;           // B col
    int bk = tid >> 4;                 // B row 0..15

    const float* Aptr = A + (size_t)(m0 + am) * lda + aq;
    const float* Bptr = B + (size_t)bk * ldb + n0 + bn;

    float acc[2][4][4];
#pragma unroll
    for (int mi = 0; mi < 2; mi++)
#pragma unroll
        for (int ni = 0; ni < 4; ni++)
#pragma unroll
            for (int r = 0; r < 4; r++) acc[mi][ni][r] = 0.f;

    float4 a0v, a1v, b0v;

    // prologue: tile 0
    a0v = *reinterpret_cast<const float4*>(Aptr);
    a1v = *reinterpret_cast<const float4*>(Aptr + 8);
    b0v = *reinterpret_cast<const float4*>(Bptr);

    As[0][aq+0][am] = tf32_of(a0v.x); As[0][aq+1][am] = tf32_of(a0v.y);
    As[0][aq+2][am] = tf32_of(a0v.z); As[0][aq+3][am] = tf32_of(a0v.w);
    As[0][aq+8][am] = tf32_of(a1v.x); As[0][aq+9][am] = tf32_of(a1v.y);
    As[0][aq+10][am] = tf32_of(a1v.z); As[0][aq+11][am] = tf32_of(a1v.w);
    Bs[0][bk][bn+0] = tf32_of(b0v.x); Bs[0][bk][bn+1] = tf32_of(b0v.y);
    Bs[0][bk][bn+2] = tf32_of(b0v.z); Bs[0][bk][bn+3] = tf32_of(b0v.w);
    __syncthreads();

    int nk = K >> 4;
    for (int it = 0; it < nk; it++) {
        int cur = it & 1;
        bool has_next = (it + 1 < nk);
        if (has_next) {
            const float* Ap = Aptr + (it + 1) * 16;
            const float* Bp = Bptr + (size_t)(it + 1) * 16 * ldb;
            a0v = *reinterpret_cast<const float4*>(Ap);
            a1v = *reinterpret_cast<const float4*>(Ap + 8);
            b0v = *reinterpret_cast<const float4*>(Bp);
        }
#pragma unroll
        for (int kk = 0; kk < 16; kk += 8) {
            uint32_t af[2][4], bf[4][2];
#pragma unroll
            for (int mi = 0; mi < 2; mi++) {
                int r = wm + mi*16 + g;
                af[mi][0] = __float_as_uint(As[cur][kk+tig  ][r    ]);
                af[mi][1] = __float_as_uint(As[cur][kk+tig  ][r + 8]);
                af[mi][2] = __float_as_uint(As[cur][kk+tig+4][r    ]);
                af[mi][3] = __float_as_uint(As[cur][kk+tig+4][r + 8]);
            }
#pragma unroll
            for (int ni = 0; ni < 4; ni++) {
                int cc = wn + ni*8 + g;
                bf[ni][0] = __float_as_uint(Bs[cur][kk+tig  ][cc]);
                bf[ni][1] = __float_as_uint(Bs[cur][kk+tig+4][cc]);
            }
#pragma unroll
            for (int mi = 0; mi < 2; mi++)
#pragma unroll
                for (int ni = 0; ni < 4; ni++)
                    mma_tf32(acc[mi][ni], af[mi], bf[ni]);
        }
        if (has_next) {
            int nb = cur ^ 1;
            As[nb][aq+0][am] = tf32_of(a0v.x); As[nb][aq+1][am] = tf32_of(a0v.y);
            As[nb][aq+2][am] = tf32_of(a0v.z); As[nb][aq+3][am] = tf32_of(a0v.w);
            As[nb][aq+8][am] = tf32_of(a1v.x); As[nb][aq+9][am] = tf32_of(a1v.y);
            As[nb][aq+10][am] = tf32_of(a1v.z); As[nb][aq+11][am] = tf32_of(a1v.w);
            Bs[nb][bk][bn+0] = tf32_of(b0v.x); Bs[nb][bk][bn+1] = tf32_of(b0v.y);
            Bs[nb][bk][bn+2] = tf32_of(b0v.z); Bs[nb][bk][bn+3] = tf32_of(b0v.w);
        }
        __syncthreads();
    }

    // epilogue
#pragma unroll
    for (int mi = 0; mi < 2; mi++) {
        int row0 = m0 + wm + mi*16 + g;
#pragma unroll
        for (int ni = 0; ni < 4; ni++) {
            int col = n0 + wn + ni*8 + 2*tig;
            float b0 = 0.f, b1 = 0.f;
            if (bias) { b0 = bias[col]; b1 = bias[col+1]; }
            float v0 = acc[mi][ni][0] + b0;
            float v1 = acc[mi][ni][1] + b1;
            float v2 = acc[mi][ni][2] + b0;
            float v3 = acc[mi][ni][3] + b1;
            if (res) {
                const float* r0p = res + (size_t)row0 * ldc + col;
                const float* r1p = res + (size_t)(row0+8) * ldc + col;
                v0 += r0p[0]; v1 += r0p[1];
                v2 += r1p[0]; v3 += r1p[1];
            }
            if (act) {
                v0 = gelu_f(v0); v1 = gelu_f(v1);
                v2 = gelu_f(v2); v3 = gelu_f(v3);
            }
            float2 o0 = make_float2(v0, v1);
            float2 o1 = make_float2(v2, v3);
            *reinterpret_cast<float2*>(C + (size_t)row0 * ldc + col)     = o0;
            *reinterpret_cast<float2*>(C + (size_t)(row0+8) * ldc + col) = o1;
        }
    }
}

// ---------------------------------------------------------------------------
// Scores: per (b,h): S = Q K^T * scale, masked; write to attn slab in d_out
// ---------------------------------------------------------------------------
__global__ __launch_bounds__(256) void score_gemm(
    const float* __restrict__ Q,
    const float* __restrict__ Kt,
    const int* __restrict__ x,
    float* __restrict__ attn, int l, float scale)
{
    __shared__ float As[64][17];
    __shared__ float Bs[16][65];
    int tid = threadIdx.x;
    int tx = tid & 15, ty = tid >> 4;
    int z = blockIdx.z;
    int b = z >> 3, hh = z & 7;
    int m0 = blockIdx.y * 64, n0 = blockIdx.x * 64;
    const float* Aq = Q  + (size_t)b*SS*DD + hh*DKV;
    const float* Bk = Kt + (size_t)b*SS*DD + hh*DKV;
    float* out = attn + (((size_t)b*LL + l)*HH + hh) * (size_t)(SS*SS);

    float acc[4][4];
#pragma unroll
    for (int r=0;r<4;r++)
#pragma unroll
        for (int c=0;c<4;c++) acc[r][c]=0.f;

    int lm = tid >> 4;
    int lk = tid & 15;

#pragma unroll
    for (int k0 = 0; k0 < DKV; k0 += 16) {
#pragma unroll
        for (int i = 0; i < 4; i++) {
            int m = lm + 16*i;
            As[m][lk] = Aq[(size_t)(m0+m)*DD + k0 + lk];
            Bs[lk][m] = Bk[(size_t)(n0+m)*DD + k0 + lk];
        }
        __syncthreads();
#pragma unroll
        for (int kk = 0; kk < 16; kk++) {
            float a[4], bfr[4];
#pragma unroll
            for (int r=0;r<4;r++) a[r]   = As[ty*4+r][kk];
#pragma unroll
            for (int c=0;c<4;c++) bfr[c] = Bs[kk][tx*4+c];
#pragma unroll
            for (int r=0;r<4;r++)
#pragma unroll
                for (int c=0;c<4;c++) acc[r][c] = fmaf(a[r], bfr[c], acc[r][c]);
        }
        __syncthreads();
    }

#pragma unroll
    for (int c = 0; c < 4; c++) {
        int n = n0 + tx*4 + c;
        bool masked = (x[b*SS + n] == 0);
#pragma unroll
        for (int r = 0; r < 4; r++) {
            int m = m0 + ty*4 + r;
            float vv = masked ? -1e9f : acc[r][c] * scale;
            out[(size_t)m*SS + n] = vv;
        }
    }
}

// ---------------------------------------------------------------------------
__global__ __launch_bounds__(128) void softmax_kernel(float* __restrict__ attn, int l)
{
    __shared__ float red[8];
    int row = blockIdx.x;
    int b = row >> 12;
    int rem = row & 4095;
    float* p = attn + (size_t)b*(LL*HH*SS*SS) + (size_t)l*(HH*SS*SS) + (size_t)rem*SS;
    int t = threadIdx.x;
    int lane = t & 31, wid = t >> 5;

    float v[4];
#pragma unroll
    for (int i = 0; i < 4; i++) v[i] = p[t + 128*i];

    float mx = fmaxf(fmaxf(v[0],v[1]), fmaxf(v[2],v[3]));
#pragma unroll
    for (int o = 16; o > 0; o >>= 1) mx = fmaxf(mx, __shfl_xor_sync(0xffffffffu, mx, o));
    if (lane == 0) red[wid] = mx;
    __syncthreads();
    mx = fmaxf(fmaxf(red[0],red[1]), fmaxf(red[2],red[3]));

    float s = 0.f;
#pragma unroll
    for (int i = 0; i < 4; i++) { v[i] = __expf(v[i] - mx); s += v[i]; }
#pragma unroll
    for (int o = 16; o > 0; o >>= 1) s += __shfl_xor_sync(0xffffffffu, s, o);
    if (lane == 0) red[4 + wid] = s;
    __syncthreads();
    s = red[4] + red[5] + red[6] + red[7];
    float inv = 1.0f / s;
#pragma unroll
    for (int i = 0; i < 4; i++) p[t + 128*i] = v[i] * inv;
}

// ---------------------------------------------------------------------------
__global__ __launch_bounds__(256) void ctx_gemm(
    const float* __restrict__ attn,
    const float* __restrict__ V,
    float* __restrict__ C, int l)
{
    __shared__ float As[64][17];
    __shared__ float Bs[16][65];
    int tid = threadIdx.x;
    int tx = tid & 15, ty = tid >> 4;
    int z = blockIdx.y;
    int b = z >> 3, hh = z & 7;
    int m0 = blockIdx.x * 64;
    const float* A  = attn + (((size_t)b*LL + l)*HH + hh) * (size_t)(SS*SS);
    const float* Bb = V + (size_t)b*SS*DD + hh*DKV;
    float* Cb = C + (size_t)b*SS*DD + hh*DKV;

    float acc[4][4];
#pragma unroll
    for (int r=0;r<4;r++)
#pragma unroll
        for (int c=0;c<4;c++) acc[r][c]=0.f;

    int lam = tid >> 4, lak = tid & 15;
    int lbn = tid & 63, lbk = tid >> 6;

    for (int k0 = 0; k0 < SS; k0 += 16) {
#pragma unroll
        for (int i = 0; i < 4; i++) {
            int m = lam + 16*i;
            As[m][lak] = A[(size_t)(m0+m)*SS + k0 + lak];
            Bs[lbk + 4*i][lbn] = Bb[(size_t)(k0 + lbk + 4*i)*DD + lbn];
        }
        __syncthreads();
#pragma unroll
        for (int kk = 0; kk < 16; kk++) {
            float a[4], bfr[4];
#pragma unroll
            for (int r=0;r<4;r++) a[r]   = As[ty*4+r][kk];
#pragma unroll
            for (int c=0;c<4;c++) bfr[c] = Bs[kk][tx*4+c];
#pragma unroll
            for (int r=0;r<4;r++)
#pragma unroll
                for (int c=0;c<4;c++) acc[r][c] = fmaf(a[r], bfr[c], acc[r][c]);
        }
        __syncthreads();
    }

#pragma unroll
    for (int r = 0; r < 4; r++) {
        int m = m0 + ty*4 + r;
#pragma unroll
        for (int c = 0; c < 4; c++) {
            int n = tx*4 + c;
            Cb[(size_t)m*DD + n] = acc[r][c];
        }
    }
}

// ---------------------------------------------------------------------------
__global__ __launch_bounds__(128) void ln_kernel(
    const float* __restrict__ in,
    const float* __restrict__ g,
    const float* __restrict__ bta,
    float* __restrict__ out)
{
    __shared__ float red[8];
    int row = blockIdx.x;
    const float* p = in + (size_t)row*DD;
    float* o = out + (size_t)row*DD;
    int t = threadIdx.x;
    int lane = t & 31, wid = t >> 5;

    float v[4];
    float s = 0.f, sq = 0.f;
#pragma unroll
    for (int i = 0; i < 4; i++) { v[i] = p[t + 128*i]; s += v[i]; sq += v[i]*v[i]; }
#pragma unroll
    for (int o2 = 16; o2 > 0; o2 >>= 1) {
        s  += __shfl_xor_sync(0xffffffffu, s,  o2);
        sq += __shfl_xor_sync(0xffffffffu, sq, o2);
    }
    if (lane == 0) { red[wid] = s; red[4+wid] = sq; }
    __syncthreads();
    s  = red[0]+red[1]+red[2]+red[3];
    sq = red[4]+red[5]+red[6]+red[7];
    float mu = s * (1.0f/DD);
    float var = sq * (1.0f/DD) - mu*mu;
    float rstd = rsqrtf(var + EPS);
#pragma unroll
    for (int i = 0; i < 4; i++) {
        int col = t + 128*i;
        o[col] = (v[i] - mu) * rstd * g[col] + bta[col];
    }
}

// ---------------------------------------------------------------------------
extern "C" void kernel_launch(void* const* d_in, const int* in_sizes, int n_in,
                              void* d_out, int out_size)
{
    const int*   x    = (const int*)  d_in[0];
    const float* emb  = (const float*)d_in[1];
    const float* pe   = (const float*)d_in[2];
    const float* WQ   = (const float*)d_in[3];
    const float* bQ   = (const float*)d_in[4];
    const float* WK   = (const float*)d_in[5];
    const float* bK   = (const float*)d_in[6];
    const float* WV   = (const float*)d_in[7];
    const float* bV   = (const float*)d_in[8];
    const float* WO   = (const float*)d_in[9];
    const float* bO   = (const float*)d_in[10];
    const float* ln1g = (const float*)d_in[11];
    const float* ln1b = (const float*)d_in[12];
    const float* W1   = (const float*)d_in[13];
    const float* b1   = (const float*)d_in[14];
    const float* W2   = (const float*)d_in[15];
    const float* b2   = (const float*)d_in[16];
    const float* ln2g = (const float*)d_in[17];
    const float* ln2b = (const float*)d_in[18];

    float* out  = (float*)d_out;
    float* attn = out + (size_t)NTOK*DD;   // h first, then attns [B,L,H,S,S]

    float *h, *q, *k, *v, *ctx, *tmp, *ff;
    cudaGetSymbolAddress((void**)&h,   g_h);
    cudaGetSymbolAddress((void**)&q,   g_q);
    cudaGetSymbolAddress((void**)&k,   g_k);
    cudaGetSymbolAddress((void**)&v,   g_v);
    cudaGetSymbolAddress((void**)&ctx, g_ctx);
    cudaGetSymbolAddress((void**)&tmp, g_tmp);
    cudaGetSymbolAddress((void**)&ff,  g_ff);

    const float scale = 0.125f; // 1/sqrt(64)

    embed_kernel<<<NTOK, 128>>>(x, emb, pe, h);

    for (int l = 0; l < LL; l++) {
        const float* wq = WQ + (size_t)l*DD*DD;
        const float* wk = WK + (size_t)l*DD*DD;
        const float* wv = WV + (size_t)l*DD*DD;
        const float* wo = WO + (size_t)l*DD*DD;
        const float* w1 = W1 + (size_t)l*DD*DFF;
        const float* w2 = W2 + (size_t)l*DFF*DD;

        // fused QKV: z selects B/bias/C
        gemm_tf32<<<dim3(8,16,3), 256>>>(h, DD,
            wq, wk, wv, DD,
            bQ + l*DD, bK + l*DD, bV + l*DD,
            nullptr,
            q, k, v, DD, DD, 0);

        score_gemm<<<dim3(8,8,32), 256>>>(q, k, x, attn, l, scale);
        softmax_kernel<<<BB*HH*SS, 128>>>(attn, l);
        ctx_gemm<<<dim3(8,32), 256>>>(attn, v, ctx, l);

        gemm_tf32<<<dim3(8,16,1), 256>>>(ctx, DD,
            wo, wo, wo, DD,
            bO + l*DD, bO + l*DD, bO + l*DD,
            h,
            tmp, tmp, tmp, DD, DD, 0);
        ln_kernel<<<NTOK, 128>>>(tmp, ln1g + l*DD, ln1b + l*DD, h);

        gemm_tf32<<<dim3(32,16,1), 256>>>(h, DD,
            w1, w1, w1, DFF,
            b1 + l*DFF, b1 + l*DFF, b1 + l*DFF,
            nullptr,
            ff, ff, ff, DFF, DD, 1);

        gemm_tf32<<<dim3(8,16,1), 256>>>(ff, DFF,
            w2, w2, w2, DD,
            b2 + l*DD, b2 + l*DD, b2 + l*DD,
            h,
            tmp, tmp, tmp, DD, DFF, 0);

        float* lnout = (l == LL-1) ? out : h;
        ln_kernel<<<NTOK, 128>>>(tmp, ln2g + l*DD, ln2b + l*DD, lnout);
    }
}

// round 4
// speedup vs baseline: 2.7936x; 1.1357x over previous
#include <cuda_runtime.h>
#include <cuda_bf16.h>
#include <math.h>
#include <stdint.h>

// Problem constants
#define BB 4
#define SS 512
#define DD 512
#define HH 8
#define DKV 64
#define DFF 2048
#define LL 6
#define NTOK (BB*SS)          // 2048
#define EPS 1e-5f

// Scratch (device globals; no allocation allowed)
__device__ __align__(128) float g_h[NTOK*DD];
__device__ __align__(128) float g_q[NTOK*DD];
__device__ __align__(128) float g_k[NTOK*DD];
__device__ __align__(128) float g_v[NTOK*DD];
__device__ __align__(128) float g_ctx[NTOK*DD];
__device__ __align__(128) float g_tmp[NTOK*DD];
__device__ __align__(128) float g_ff[NTOK*DFF];

// ---------------------------------------------------------------------------
__global__ void embed_kernel(const int* __restrict__ x,
                             const float* __restrict__ emb,
                             const float* __restrict__ pe,
                             float* __restrict__ h)
{
    int tok = blockIdx.x;
    int s = tok & (SS-1);
    int id = x[tok];
    int t = threadIdx.x; // 0..127
    const float4* e4 = reinterpret_cast<const float4*>(emb + (size_t)id*DD);
    const float4* p4 = reinterpret_cast<const float4*>(pe + (size_t)s*DD);
    float4 ev = e4[t], pv = p4[t];
    float4 r; r.x=ev.x+pv.x; r.y=ev.y+pv.y; r.z=ev.z+pv.z; r.w=ev.w+pv.w;
    reinterpret_cast<float4*>(h + (size_t)tok*DD)[t] = r;
}

__device__ __forceinline__ float gelu_f(float x) {
    return 0.5f * x * (1.0f + tanhf(0.7978845608028654f * (x + 0.044715f*x*x*x)));
}

__device__ __forceinline__ float tf32_of(float x) {
    uint32_t u;
    asm("cvt.rna.tf32.f32 %0, %1;" : "=r"(u) : "f"(x));
    return __uint_as_float(u);
}

__device__ __forceinline__ void mma_tf32(float* c, const uint32_t* a, const uint32_t* b) {
    asm volatile(
        "mma.sync.aligned.m16n8k8.row.col.f32.tf32.tf32.f32 "
        "{%0,%1,%2,%3}, {%4,%5,%6,%7}, {%8,%9}, {%0,%1,%2,%3};"
        : "+f"(c[0]), "+f"(c[1]), "+f"(c[2]), "+f"(c[3])
        : "r"(a[0]), "r"(a[1]), "r"(a[2]), "r"(a[3]), "r"(b[0]), "r"(b[1]));
}

// ---------------------------------------------------------------------------
// TF32 tensor-core GEMM: C[M,N] = A[M,K] @ B[K,N] (+bias)(+res)(+gelu)
// CTA tile 128(M) x 64(N), BK=16, 256 threads (8 warps: 4m x 2n, 32x32 warp).
// blockIdx.z selects among up to 3 (B, bias, C) triples (QKV fusion).
// grid: (N/64, M/128, nz)
// ---------------------------------------------------------------------------
__global__ __launch_bounds__(256) void gemm_tf32(
    const float* __restrict__ A, int lda,
    const float* __restrict__ B0, const float* __restrict__ B1, const float* __restrict__ B2,
    int ldb,
    const float* __restrict__ bias0, const float* __restrict__ bias1, const float* __restrict__ bias2,
    const float* __restrict__ res,
    float* __restrict__ C0, float* __restrict__ C1, float* __restrict__ C2,
    int ldc, int K, int act)
{
    int z = blockIdx.z;
    const float* B    = (z == 0) ? B0    : ((z == 1) ? B1    : B2);
    const float* bias = (z == 0) ? bias0 : ((z == 1) ? bias1 : bias2);
    float*       C    = (z == 0) ? C0    : ((z == 1) ? C1    : C2);

    __shared__ float As[2][16][136];
    __shared__ float Bs[2][16][72];

    int tid  = threadIdx.x;
    int lane = tid & 31, warp = tid >> 5;
    int g    = lane >> 2, tig = lane & 3;
    int wm   = (warp & 3) * 32;
    int wn   = (warp >> 2) * 32;
    int m0   = blockIdx.y * 128, n0 = blockIdx.x * 64;

    int am = tid & 127;
    int aq = (tid >> 7) * 4;
    int bn = (tid & 15) * 4;
    int bk = tid >> 4;

    const float* Aptr = A + (size_t)(m0 + am) * lda + aq;
    const float* Bptr = B + (size_t)bk * ldb + n0 + bn;

    float acc[2][4][4];
#pragma unroll
    for (int mi = 0; mi < 2; mi++)
#pragma unroll
        for (int ni = 0; ni < 4; ni++)
#pragma unroll
            for (int r = 0; r < 4; r++) acc[mi][ni][r] = 0.f;

    float4 a0v, a1v, b0v;

    a0v = *reinterpret_cast<const float4*>(Aptr);
    a1v = *reinterpret_cast<const float4*>(Aptr + 8);
    b0v = *reinterpret_cast<const float4*>(Bptr);

    As[0][aq+0][am] = tf32_of(a0v.x); As[0][aq+1][am] = tf32_of(a0v.y);
    As[0][aq+2][am] = tf32_of(a0v.z); As[0][aq+3][am] = tf32_of(a0v.w);
    As[0][aq+8][am] = tf32_of(a1v.x); As[0][aq+9][am] = tf32_of(a1v.y);
    As[0][aq+10][am] = tf32_of(a1v.z); As[0][aq+11][am] = tf32_of(a1v.w);
    Bs[0][bk][bn+0] = tf32_of(b0v.x); Bs[0][bk][bn+1] = tf32_of(b0v.y);
    Bs[0][bk][bn+2] = tf32_of(b0v.z); Bs[0][bk][bn+3] = tf32_of(b0v.w);
    __syncthreads();

    int nk = K >> 4;
    for (int it = 0; it < nk; it++) {
        int cur = it & 1;
        bool has_next = (it + 1 < nk);
        if (has_next) {
            const float* Ap = Aptr + (it + 1) * 16;
            const float* Bp = Bptr + (size_t)(it + 1) * 16 * ldb;
            a0v = *reinterpret_cast<const float4*>(Ap);
            a1v = *reinterpret_cast<const float4*>(Ap + 8);
            b0v = *reinterpret_cast<const float4*>(Bp);
        }
#pragma unroll
        for (int kk = 0; kk < 16; kk += 8) {
            uint32_t af[2][4], bf[4][2];
#pragma unroll
            for (int mi = 0; mi < 2; mi++) {
                int r = wm + mi*16 + g;
                af[mi][0] = __float_as_uint(As[cur][kk+tig  ][r    ]);
                af[mi][1] = __float_as_uint(As[cur][kk+tig  ][r + 8]);
                af[mi][2] = __float_as_uint(As[cur][kk+tig+4][r    ]);
                af[mi][3] = __float_as_uint(As[cur][kk+tig+4][r + 8]);
            }
#pragma unroll
            for (int ni = 0; ni < 4; ni++) {
                int cc = wn + ni*8 + g;
                bf[ni][0] = __float_as_uint(Bs[cur][kk+tig  ][cc]);
                bf[ni][1] = __float_as_uint(Bs[cur][kk+tig+4][cc]);
            }
#pragma unroll
            for (int mi = 0; mi < 2; mi++)
#pragma unroll
                for (int ni = 0; ni < 4; ni++)
                    mma_tf32(acc[mi][ni], af[mi], bf[ni]);
        }
        if (has_next) {
            int nb = cur ^ 1;
            As[nb][aq+0][am] = tf32_of(a0v.x); As[nb][aq+1][am] = tf32_of(a0v.y);
            As[nb][aq+2][am] = tf32_of(a0v.z); As[nb][aq+3][am] = tf32_of(a0v.w);
            As[nb][aq+8][am] = tf32_of(a1v.x); As[nb][aq+9][am] = tf32_of(a1v.y);
            As[nb][aq+10][am] = tf32_of(a1v.z); As[nb][aq+11][am] = tf32_of(a1v.w);
            Bs[nb][bk][bn+0] = tf32_of(b0v.x); Bs[nb][bk][bn+1] = tf32_of(b0v.y);
            Bs[nb][bk][bn+2] = tf32_of(b0v.z); Bs[nb][bk][bn+3] = tf32_of(b0v.w);
        }
        __syncthreads();
    }

#pragma unroll
    for (int mi = 0; mi < 2; mi++) {
        int row0 = m0 + wm + mi*16 + g;
#pragma unroll
        for (int ni = 0; ni < 4; ni++) {
            int col = n0 + wn + ni*8 + 2*tig;
            float b0 = 0.f, b1 = 0.f;
            if (bias) { b0 = bias[col]; b1 = bias[col+1]; }
            float v0 = acc[mi][ni][0] + b0;
            float v1 = acc[mi][ni][1] + b1;
            float v2 = acc[mi][ni][2] + b0;
            float v3 = acc[mi][ni][3] + b1;
            if (res) {
                const float* r0p = res + (size_t)row0 * ldc + col;
                const float* r1p = res + (size_t)(row0+8) * ldc + col;
                v0 += r0p[0]; v1 += r0p[1];
                v2 += r1p[0]; v3 += r1p[1];
            }
            if (act) {
                v0 = gelu_f(v0); v1 = gelu_f(v1);
                v2 = gelu_f(v2); v3 = gelu_f(v3);
            }
            *reinterpret_cast<float2*>(C + (size_t)row0 * ldc + col)     = make_float2(v0, v1);
            *reinterpret_cast<float2*>(C + (size_t)(row0+8) * ldc + col) = make_float2(v2, v3);
        }
    }
}

// ---------------------------------------------------------------------------
// TF32 score GEMM: per (b,h) S[512,512] = Q[512,64] @ K[512,64]^T * scale, mask
// CTA 128(M q-rows) x 64(N k-rows), K=64. 256 threads, 8 warps (4m x 2n).
// grid (8 ntile, 4 mtile, 32 bh). Both A and B are K-major rows (ld = DD).
// ---------------------------------------------------------------------------
__global__ __launch_bounds__(256) void score_tf32(
    const float* __restrict__ Q,
    const float* __restrict__ Kmat,
    const int* __restrict__ x,
    float* __restrict__ attn, int l, float scale)
{
    __shared__ float As[2][16][136];
    __shared__ float Bs[2][16][72];

    int tid  = threadIdx.x;
    int lane = tid & 31, warp = tid >> 5;
    int g    = lane >> 2, tig = lane & 3;
    int wm   = (warp & 3) * 32;
    int wn   = (warp >> 2) * 32;
    int zz = blockIdx.z;
    int b = zz >> 3, hh = zz & 7;
    int m0 = blockIdx.y * 128, n0 = blockIdx.x * 64;

    const float* Abase = Q    + (size_t)b*SS*DD + hh*DKV;
    const float* Bbase = Kmat + (size_t)b*SS*DD + hh*DKV;
    float* out = attn + (((size_t)b*LL + l)*HH + hh) * (size_t)(SS*SS);

    // A loader: 128 rows x 16 k (2 float4 per thread)
    int am = tid & 127;
    int aq = (tid >> 7) * 4;
    // B loader: 64 rows x 16 k (2 float4 per thread), 64 rows x 2 halves
    int bm = tid & 63;
    int bq = (tid >> 6) * 4;  // 0,4,8,12

    const float* Aptr = Abase + (size_t)(m0 + am) * DD + aq;
    const float* Bptr = Bbase + (size_t)(n0 + bm) * DD + bq;

    float acc[2][4][4];
#pragma unroll
    for (int mi = 0; mi < 2; mi++)
#pragma unroll
        for (int ni = 0; ni < 4; ni++)
#pragma unroll
            for (int r = 0; r < 4; r++) acc[mi][ni][r] = 0.f;

    float4 a0v, a1v, b0v;

    a0v = *reinterpret_cast<const float4*>(Aptr);
    a1v = *reinterpret_cast<const float4*>(Aptr + 8);
    b0v = *reinterpret_cast<const float4*>(Bptr);

    As[0][aq+0][am] = tf32_of(a0v.x); As[0][aq+1][am] = tf32_of(a0v.y);
    As[0][aq+2][am] = tf32_of(a0v.z); As[0][aq+3][am] = tf32_of(a0v.w);
    As[0][aq+8][am] = tf32_of(a1v.x); As[0][aq+9][am] = tf32_of(a1v.y);
    As[0][aq+10][am] = tf32_of(a1v.z); As[0][aq+11][am] = tf32_of(a1v.w);
    Bs[0][bq+0][bm] = tf32_of(b0v.x); Bs[0][bq+1][bm] = tf32_of(b0v.y);
    Bs[0][bq+2][bm] = tf32_of(b0v.z); Bs[0][bq+3][bm] = tf32_of(b0v.w);
    __syncthreads();

    const int nk = DKV >> 4;  // 4
#pragma unroll
    for (int it = 0; it < nk; it++) {
        int cur = it & 1;
        bool has_next = (it + 1 < nk);
        if (has_next) {
            const float* Ap = Aptr + (it + 1) * 16;
            const float* Bp = Bptr + (it + 1) * 16;
            a0v = *reinterpret_cast<const float4*>(Ap);
            a1v = *reinterpret_cast<const float4*>(Ap + 8);
            b0v = *reinterpret_cast<const float4*>(Bp);
        }
#pragma unroll
        for (int kk = 0; kk < 16; kk += 8) {
            uint32_t af[2][4], bf[4][2];
#pragma unroll
            for (int mi = 0; mi < 2; mi++) {
                int r = wm + mi*16 + g;
                af[mi][0] = __float_as_uint(As[cur][kk+tig  ][r    ]);
                af[mi][1] = __float_as_uint(As[cur][kk+tig  ][r + 8]);
                af[mi][2] = __float_as_uint(As[cur][kk+tig+4][r    ]);
                af[mi][3] = __float_as_uint(As[cur][kk+tig+4][r + 8]);
            }
#pragma unroll
            for (int ni = 0; ni < 4; ni++) {
                int cc = wn + ni*8 + g;
                bf[ni][0] = __float_as_uint(Bs[cur][kk+tig  ][cc]);
                bf[ni][1] = __float_as_uint(Bs[cur][kk+tig+4][cc]);
            }
#pragma unroll
            for (int mi = 0; mi < 2; mi++)
#pragma unroll
                for (int ni = 0; ni < 4; ni++)
                    mma_tf32(acc[mi][ni], af[mi], bf[ni]);
        }
        if (has_next) {
            int nb = cur ^ 1;
            As[nb][aq+0][am] = tf32_of(a0v.x); As[nb][aq+1][am] = tf32_of(a0v.y);
            As[nb][aq+2][am] = tf32_of(a0v.z); As[nb][aq+3][am] = tf32_of(a0v.w);
            As[nb][aq+8][am] = tf32_of(a1v.x); As[nb][aq+9][am] = tf32_of(a1v.y);
            As[nb][aq+10][am] = tf32_of(a1v.z); As[nb][aq+11][am] = tf32_of(a1v.w);
            Bs[nb][bq+0][bm] = tf32_of(b0v.x); Bs[nb][bq+1][bm] = tf32_of(b0v.y);
            Bs[nb][bq+2][bm] = tf32_of(b0v.z); Bs[nb][bq+3][bm] = tf32_of(b0v.w);
        }
        __syncthreads();
    }

    const int* xb = x + b*SS;
#pragma unroll
    for (int mi = 0; mi < 2; mi++) {
        int row0 = m0 + wm + mi*16 + g;
#pragma unroll
        for (int ni = 0; ni < 4; ni++) {
            int col = n0 + wn + ni*8 + 2*tig;
            bool msk0 = (xb[col]   == 0);
            bool msk1 = (xb[col+1] == 0);
            float v0 = msk0 ? -1e9f : acc[mi][ni][0] * scale;
            float v1 = msk1 ? -1e9f : acc[mi][ni][1] * scale;
            float v2 = msk0 ? -1e9f : acc[mi][ni][2] * scale;
            float v3 = msk1 ? -1e9f : acc[mi][ni][3] * scale;
            *reinterpret_cast<float2*>(out + (size_t)row0 * SS + col)     = make_float2(v0, v1);
            *reinterpret_cast<float2*>(out + (size_t)(row0+8) * SS + col) = make_float2(v2, v3);
        }
    }
}

// ---------------------------------------------------------------------------
// TF32 ctx GEMM: per (b,h) C[512,64] = P[512,512] @ V[512,64]
// CTA 128(M) x 64(N), K=512 (BK=16). grid (4 mtile, 32 bh). 256 threads.
// ---------------------------------------------------------------------------
__global__ __launch_bounds__(256) void ctx_tf32(
    const float* __restrict__ attn,
    const float* __restrict__ V,
    float* __restrict__ C, int l)
{
    __shared__ float As[2][16][136];
    __shared__ float Bs[2][16][72];

    int tid  = threadIdx.x;
    int lane = tid & 31, warp = tid >> 5;
    int g    = lane >> 2, tig = lane & 3;
    int wm   = (warp & 3) * 32;
    int wn   = (warp >> 2) * 32;
    int zz = blockIdx.y;
    int b = zz >> 3, hh = zz & 7;
    int m0 = blockIdx.x * 128;

    const float* Abase = attn + (((size_t)b*LL + l)*HH + hh) * (size_t)(SS*SS);
    const float* Bbase = V + (size_t)b*SS*DD + hh*DKV;
    float* Cb = C + (size_t)b*SS*DD + hh*DKV;

    int am = tid & 127;
    int aq = (tid >> 7) * 4;
    int bn = (tid & 15) * 4;
    int bk = tid >> 4;

    const float* Aptr = Abase + (size_t)(m0 + am) * SS + aq;
    const float* Bptr = Bbase + (size_t)bk * DD + bn;

    float acc[2][4][4];
#pragma unroll
    for (int mi = 0; mi < 2; mi++)
#pragma unroll
        for (int ni = 0; ni < 4; ni++)
#pragma unroll
            for (int r = 0; r < 4; r++) acc[mi][ni][r] = 0.f;

    float4 a0v, a1v, b0v;

    a0v = *reinterpret_cast<const float4*>(Aptr);
    a1v = *reinterpret_cast<const float4*>(Aptr + 8);
    b0v = *reinterpret_cast<const float4*>(Bptr);

    As[0][aq+0][am] = tf32_of(a0v.x); As[0][aq+1][am] = tf32_of(a0v.y);
    As[0][aq+2][am] = tf32_of(a0v.z); As[0][aq+3][am] = tf32_of(a0v.w);
    As[0][aq+8][am] = tf32_of(a1v.x); As[0][aq+9][am] = tf32_of(a1v.y);
    As[0][aq+10][am] = tf32_of(a1v.z); As[0][aq+11][am] = tf32_of(a1v.w);
    Bs[0][bk][bn+0] = tf32_of(b0v.x); Bs[0][bk][bn+1] = tf32_of(b0v.y);
    Bs[0][bk][bn+2] = tf32_of(b0v.z); Bs[0][bk][bn+3] = tf32_of(b0v.w);
    __syncthreads();

    const int nk = SS >> 4;  // 32
    for (int it = 0; it < nk; it++) {
        int cur = it & 1;
        bool has_next = (it + 1 < nk);
        if (has_next) {
            const float* Ap = Aptr + (it + 1) * 16;
            const float* Bp = Bptr + (size_t)(it + 1) * 16 * DD;
            a0v = *reinterpret_cast<const float4*>(Ap);
            a1v = *reinterpret_cast<const float4*>(Ap + 8);
            b0v = *reinterpret_cast<const float4*>(Bp);
        }
#pragma unroll
        for (int kk = 0; kk < 16; kk += 8) {
            uint32_t af[2][4], bf[4][2];
#pragma unroll
            for (int mi = 0; mi < 2; mi++) {
                int r = wm + mi*16 + g;
                af[mi][0] = __float_as_uint(As[cur][kk+tig  ][r    ]);
                af[mi][1] = __float_as_uint(As[cur][kk+tig  ][r + 8]);
                af[mi][2] = __float_as_uint(As[cur][kk+tig+4][r    ]);
                af[mi][3] = __float_as_uint(As[cur][kk+tig+4][r + 8]);
            }
#pragma unroll
            for (int ni = 0; ni < 4; ni++) {
                int cc = wn + ni*8 + g;
                bf[ni][0] = __float_as_uint(Bs[cur][kk+tig  ][cc]);
                bf[ni][1] = __float_as_uint(Bs[cur][kk+tig+4][cc]);
            }
#pragma unroll
            for (int mi = 0; mi < 2; mi++)
#pragma unroll
                for (int ni = 0; ni < 4; ni++)
                    mma_tf32(acc[mi][ni], af[mi], bf[ni]);
        }
        if (has_next) {
            int nb = cur ^ 1;
            As[nb][aq+0][am] = tf32_of(a0v.x); As[nb][aq+1][am] = tf32_of(a0v.y);
            As[nb][aq+2][am] = tf32_of(a0v.z); As[nb][aq+3][am] = tf32_of(a0v.w);
            As[nb][aq+8][am] = tf32_of(a1v.x); As[nb][aq+9][am] = tf32_of(a1v.y);
            As[nb][aq+10][am] = tf32_of(a1v.z); As[nb][aq+11][am] = tf32_of(a1v.w);
            Bs[nb][bk][bn+0] = tf32_of(b0v.x); Bs[nb][bk][bn+1] = tf32_of(b0v.y);
            Bs[nb][bk][bn+2] = tf32_of(b0v.z); Bs[nb][bk][bn+3] = tf32_of(b0v.w);
        }
        __syncthreads();
    }

#pragma unroll
    for (int mi = 0; mi < 2; mi++) {
        int row0 = m0 + wm + mi*16 + g;
#pragma unroll
        for (int ni = 0; ni < 4; ni++) {
            int col = wn + ni*8 + 2*tig;
            *reinterpret_cast<float2*>(Cb + (size_t)row0 * DD + col)
                = make_float2(acc[mi][ni][0], acc[mi][ni][1]);
            *reinterpret_cast<float2*>(Cb + (size_t)(row0+8) * DD + col)
                = make_float2(acc[mi][ni][2], acc[mi][ni][3]);
        }
    }
}

// ---------------------------------------------------------------------------
__global__ __launch_bounds__(128) void softmax_kernel(float* __restrict__ attn, int l)
{
    __shared__ float red[8];
    int row = blockIdx.x;
    int b = row >> 12;
    int rem = row & 4095;
    float* p = attn + (size_t)b*(LL*HH*SS*SS) + (size_t)l*(HH*SS*SS) + (size_t)rem*SS;
    int t = threadIdx.x;
    int lane = t & 31, wid = t >> 5;

    float v[4];
#pragma unroll
    for (int i = 0; i < 4; i++) v[i] = p[t + 128*i];

    float mx = fmaxf(fmaxf(v[0],v[1]), fmaxf(v[2],v[3]));
#pragma unroll
    for (int o = 16; o > 0; o >>= 1) mx = fmaxf(mx, __shfl_xor_sync(0xffffffffu, mx, o));
    if (lane == 0) red[wid] = mx;
    __syncthreads();
    mx = fmaxf(fmaxf(red[0],red[1]), fmaxf(red[2],red[3]));

    float s = 0.f;
#pragma unroll
    for (int i = 0; i < 4; i++) { v[i] = __expf(v[i] - mx); s += v[i]; }
#pragma unroll
    for (int o = 16; o > 0; o >>= 1) s += __shfl_xor_sync(0xffffffffu, s, o);
    if (lane == 0) red[4 + wid] = s;
    __syncthreads();
    s = red[4] + red[5] + red[6] + red[7];
    float inv = 1.0f / s;
#pragma unroll
    for (int i = 0; i < 4; i++) p[t + 128*i] = v[i] * inv;
}

// ---------------------------------------------------------------------------
__global__ __launch_bounds__(128) void ln_kernel(
    const float* __restrict__ in,
    const float* __restrict__ g,
    const float* __restrict__ bta,
    float* __restrict__ out)
{
    __shared__ float red[8];
    int row = blockIdx.x;
    const float* p = in + (size_t)row*DD;
    float* o = out + (size_t)row*DD;
    int t = threadIdx.x;
    int lane = t & 31, wid = t >> 5;

    float v[4];
    float s = 0.f, sq = 0.f;
#pragma unroll
    for (int i = 0; i < 4; i++) { v[i] = p[t + 128*i]; s += v[i]; sq += v[i]*v[i]; }
#pragma unroll
    for (int o2 = 16; o2 > 0; o2 >>= 1) {
        s  += __shfl_xor_sync(0xffffffffu, s,  o2);
        sq += __shfl_xor_sync(0xffffffffu, sq, o2);
    }
    if (lane == 0) { red[wid] = s; red[4+wid] = sq; }
    __syncthreads();
    s  = red[0]+red[1]+red[2]+red[3];
    sq = red[4]+red[5]+red[6]+red[7];
    float mu = s * (1.0f/DD);
    float var = sq * (1.0f/DD) - mu*mu;
    float rstd = rsqrtf(var + EPS);
#pragma unroll
    for (int i = 0; i < 4; i++) {
        int col = t + 128*i;
        o[col] = (v[i] - mu) * rstd * g[col] + bta[col];
    }
}

// ---------------------------------------------------------------------------
extern "C" void kernel_launch(void* const* d_in, const int* in_sizes, int n_in,
                              void* d_out, int out_size)
{
    const int*   x    = (const int*)  d_in[0];
    const float* emb  = (const float*)d_in[1];
    const float* pe   = (const float*)d_in[2];
    const float* WQ   = (const float*)d_in[3];
    const float* bQ   = (const float*)d_in[4];
    const float* WK   = (const float*)d_in[5];
    const float* bK   = (const float*)d_in[6];
    const float* WV   = (const float*)d_in[7];
    const float* bV   = (const float*)d_in[8];
    const float* WO   = (const float*)d_in[9];
    const float* bO   = (const float*)d_in[10];
    const float* ln1g = (const float*)d_in[11];
    const float* ln1b = (const float*)d_in[12];
    const float* W1   = (const float*)d_in[13];
    const float* b1   = (const float*)d_in[14];
    const float* W2   = (const float*)d_in[15];
    const float* b2   = (const float*)d_in[16];
    const float* ln2g = (const float*)d_in[17];
    const float* ln2b = (const float*)d_in[18];

    float* out  = (float*)d_out;
    float* attn = out + (size_t)NTOK*DD;

    float *h, *q, *k, *v, *ctx, *tmp, *ff;
    cudaGetSymbolAddress((void**)&h,   g_h);
    cudaGetSymbolAddress((void**)&q,   g_q);
    cudaGetSymbolAddress((void**)&k,   g_k);
    cudaGetSymbolAddress((void**)&v,   g_v);
    cudaGetSymbolAddress((void**)&ctx, g_ctx);
    cudaGetSymbolAddress((void**)&tmp, g_tmp);
    cudaGetSymbolAddress((void**)&ff,  g_ff);

    const float scale = 0.125f;

    embed_kernel<<<NTOK, 128>>>(x, emb, pe, h);

    for (int l = 0; l < LL; l++) {
        const float* wq = WQ + (size_t)l*DD*DD;
        const float* wk = WK + (size_t)l*DD*DD;
        const float* wv = WV + (size_t)l*DD*DD;
        const float* wo = WO + (size_t)l*DD*DD;
        const float* w1 = W1 + (size_t)l*DD*DFF;
        const float* w2 = W2 + (size_t)l*DFF*DD;

        gemm_tf32<<<dim3(8,16,3), 256>>>(h, DD,
            wq, wk, wv, DD,
            bQ + l*DD, bK + l*DD, bV + l*DD,
            nullptr,
            q, k, v, DD, DD, 0);

        score_tf32<<<dim3(8,4,32), 256>>>(q, k, x, attn, l, scale);
        softmax_kernel<<<BB*HH*SS, 128>>>(attn, l);
        ctx_tf32<<<dim3(4,32), 256>>>(attn, v, ctx, l);

        gemm_tf32<<<dim3(8,16,1), 256>>>(ctx, DD,
            wo, wo, wo, DD,
            bO + l*DD, bO + l*DD, bO + l*DD,
            h,
            tmp, tmp, tmp, DD, DD, 0);
        ln_kernel<<<NTOK, 128>>>(tmp, ln1g + l*DD, ln1b + l*DD, h);

        gemm_tf32<<<dim3(32,16,1), 256>>>(h, DD,
            w1, w1, w1, DFF,
            b1 + l*DFF, b1 + l*DFF, b1 + l*DFF,
            nullptr,
            ff, ff, ff, DFF, DD, 1);

        gemm_tf32<<<dim3(8,16,1), 256>>>(ff, DFF,
            w2, w2, w2, DD,
            b2 + l*DD, b2 + l*DD, b2 + l*DD,
            h,
            tmp, tmp, tmp, DD, DFF, 0);

        float* lnout = (l == LL-1) ? out : h;
        ln_kernel<<<NTOK, 128>>>(tmp, ln2g + l*DD, ln2b + l*DD, lnout);
    }
}

// round 6
// speedup vs baseline: 4.3601x; 1.5608x over previous
#include <cuda_runtime.h>
#include <cuda_bf16.h>
#include <math.h>
#include <stdint.h>

// Problem constants
#define BB 4
#define SS 512
#define DD 512
#define HH 8
#define DKV 64
#define DFF 2048
#define LL 6
#define NTOK (BB*SS)          // 2048
#define EPS 1e-5f

// Scratch (device globals; no allocation allowed)
__device__ __align__(128) float g_h[NTOK*DD];
__device__ __align__(128) float g_q[NTOK*DD];
__device__ __align__(128) float g_k[NTOK*DD];
__device__ __align__(128) float g_v[NTOK*DD];
__device__ __align__(128) float g_ctx[NTOK*DD];
__device__ __align__(128) float g_tmp[NTOK*DD];
__device__ __align__(128) float g_ff[NTOK*DFF];

// ---------------------------------------------------------------------------
__global__ void embed_kernel(const int* __restrict__ x,
                             const float* __restrict__ emb,
                             const float* __restrict__ pe,
                             float* __restrict__ h)
{
    int tok = blockIdx.x;
    int s = tok & (SS-1);
    int id = x[tok];
    int t = threadIdx.x; // 0..127
    const float4* e4 = reinterpret_cast<const float4*>(emb + (size_t)id*DD);
    const float4* p4 = reinterpret_cast<const float4*>(pe + (size_t)s*DD);
    float4 ev = e4[t], pv = p4[t];
    float4 r; r.x=ev.x+pv.x; r.y=ev.y+pv.y; r.z=ev.z+pv.z; r.w=ev.w+pv.w;
    reinterpret_cast<float4*>(h + (size_t)tok*DD)[t] = r;
}

__device__ __forceinline__ float gelu_f(float x) {
    return 0.5f * x * (1.0f + tanhf(0.7978845608028654f * (x + 0.044715f*x*x*x)));
}

__device__ __forceinline__ uint32_t tf32u(float x) {
    uint32_t u;
    asm("cvt.rna.tf32.f32 %0, %1;" : "=r"(u) : "f"(x));
    return u;
}

__device__ __forceinline__ void mma_tf32(float* c, const uint32_t* a, const uint32_t* b) {
    asm volatile(
        "mma.sync.aligned.m16n8k8.row.col.f32.tf32.tf32.f32 "
        "{%0,%1,%2,%3}, {%4,%5,%6,%7}, {%8,%9}, {%0,%1,%2,%3};"
        : "+f"(c[0]), "+f"(c[1]), "+f"(c[2]), "+f"(c[3])
        : "r"(a[0]), "r"(a[1]), "r"(a[2]), "r"(a[3]), "r"(b[0]), "r"(b[1]));
}

__device__ __forceinline__ void cp16(void* smem_dst, const void* gsrc) {
    uint32_t s = (uint32_t)__cvta_generic_to_shared(smem_dst);
    asm volatile("cp.async.cg.shared.global [%0], [%1], 16;" :: "r"(s), "l"(gsrc));
}
#define CP_COMMIT() asm volatile("cp.async.commit_group;")
#define CP_WAIT1()  asm volatile("cp.async.wait_group 1;")
#define CP_WAIT0()  asm volatile("cp.async.wait_group 0;")

// ---------------------------------------------------------------------------
// Pipelined TF32 GEMM: C[M,N] = A[M,K] @ B[K,N] (+bias)(+res)(+gelu)
// CTA 128(M) x 64(N), BK=16, 3-stage cp.async pipeline, 256 threads,
// 8 warps (4m x 2n), warp tile 32x32. blockIdx.z selects (B,bias,C) triple.
// grid: (N/64, M/128, nz)
// ---------------------------------------------------------------------------
__global__ __launch_bounds__(256, 2) void gemm_tf32p(
    const float* __restrict__ A, int lda,
    const float* __restrict__ B0, const float* __restrict__ B1, const float* __restrict__ B2,
    int ldb,
    const float* __restrict__ bias0, const float* __restrict__ bias1, const float* __restrict__ bias2,
    const float* __restrict__ res,
    float* __restrict__ C0, float* __restrict__ C1, float* __restrict__ C2,
    int ldc, int K, int act)
{
    int z = blockIdx.z;
    const float* B    = (z == 0) ? B0    : ((z == 1) ? B1    : B2);
    const float* bias = (z == 0) ? bias0 : ((z == 1) ? bias1 : bias2);
    float*       C    = (z == 0) ? C0    : ((z == 1) ? C1    : C2);

    __shared__ float As[3][128][20];   // [m][k], pad->20 (conflict-free frags)
    __shared__ float Bs[3][16][72];    // [k][n], pad->72 (stride % 32 == 8)

    int tid  = threadIdx.x;
    int lane = tid & 31, warp = tid >> 5;
    int g    = lane >> 2, tig = lane & 3;
    int wm   = (warp & 3) * 32;
    int wn   = (warp >> 2) * 32;
    int m0   = blockIdx.y * 128, n0 = blockIdx.x * 64;

    // cp.async loaders
    int arow = tid >> 1, acol = (tid & 1) * 8;     // 128 rows x 16 k, 32B/thread (2 cp16)
    int brow = tid >> 4, bcol = (tid & 15) * 4;    // 16 rows x 64 n, 16B/thread (1 cp16)

    const float* Aptr = A + (size_t)(m0 + arow) * lda + acol;
    const float* Bptr = B + (size_t)brow * ldb + n0 + bcol;

    float acc[2][4][4];
#pragma unroll
    for (int mi = 0; mi < 2; mi++)
#pragma unroll
        for (int ni = 0; ni < 4; ni++)
#pragma unroll
            for (int r = 0; r < 4; r++) acc[mi][ni][r] = 0.f;

    int nk = K >> 4;

    // prologue: issue 2 stages
#pragma unroll
    for (int s = 0; s < 2; s++) {
        int k0 = s * 16;
        cp16(&As[s][arow][acol],     Aptr + k0);
        cp16(&As[s][arow][acol + 4], Aptr + k0 + 4);
        cp16(&Bs[s][brow][bcol],     Bptr + (size_t)k0 * ldb);
        CP_COMMIT();
    }

    for (int it = 0; it < nk; it++) {
        if (it + 1 < nk) CP_WAIT1(); else CP_WAIT0();
        __syncthreads();
        int s = it % 3;
#pragma unroll
        for (int kk = 0; kk < 16; kk += 8) {
            uint32_t af[2][4], bf[4][2];
#pragma unroll
            for (int mi = 0; mi < 2; mi++) {
                int r = wm + mi*16 + g;
                af[mi][0] = tf32u(As[s][r    ][kk+tig  ]);
                af[mi][1] = tf32u(As[s][r + 8][kk+tig  ]);
                af[mi][2] = tf32u(As[s][r    ][kk+tig+4]);
                af[mi][3] = tf32u(As[s][r + 8][kk+tig+4]);
            }
#pragma unroll
            for (int ni = 0; ni < 4; ni++) {
                int cc = wn + ni*8 + g;
                bf[ni][0] = tf32u(Bs[s][kk+tig  ][cc]);
                bf[ni][1] = tf32u(Bs[s][kk+tig+4][cc]);
            }
#pragma unroll
            for (int mi = 0; mi < 2; mi++)
#pragma unroll
                for (int ni = 0; ni < 4; ni++)
                    mma_tf32(acc[mi][ni], af[mi], bf[ni]);
        }
        int nx = it + 2;
        if (nx < nk) {
            int sn = nx % 3;
            int k0 = nx * 16;
            cp16(&As[sn][arow][acol],     Aptr + k0);
            cp16(&As[sn][arow][acol + 4], Aptr + k0 + 4);
            cp16(&Bs[sn][brow][bcol],     Bptr + (size_t)k0 * ldb);
            CP_COMMIT();
        }
        __syncthreads();
    }

#pragma unroll
    for (int mi = 0; mi < 2; mi++) {
        int row0 = m0 + wm + mi*16 + g;
#pragma unroll
        for (int ni = 0; ni < 4; ni++) {
            int col = n0 + wn + ni*8 + 2*tig;
            float b0 = 0.f, b1 = 0.f;
            if (bias) { b0 = bias[col]; b1 = bias[col+1]; }
            float v0 = acc[mi][ni][0] + b0;
            float v1 = acc[mi][ni][1] + b1;
            float v2 = acc[mi][ni][2] + b0;
            float v3 = acc[mi][ni][3] + b1;
            if (res) {
                const float* r0p = res + (size_t)row0 * ldc + col;
                const float* r1p = res + (size_t)(row0+8) * ldc + col;
                v0 += r0p[0]; v1 += r0p[1];
                v2 += r1p[0]; v3 += r1p[1];
            }
            if (act) {
                v0 = gelu_f(v0); v1 = gelu_f(v1);
                v2 = gelu_f(v2); v3 = gelu_f(v3);
            }
            *reinterpret_cast<float2*>(C + (size_t)row0 * ldc + col)     = make_float2(v0, v1);
            *reinterpret_cast<float2*>(C + (size_t)(row0+8) * ldc + col) = make_float2(v2, v3);
        }
    }
}

// ---------------------------------------------------------------------------
// Pipelined TF32 score GEMM: per (b,h) S = Q @ K^T * scale + mask
// CTA 128(M) x 64(N kv rows), K=64. B smem layout [n][k] (row of K-matrix).
// grid (8 ntile, 4 mtile, 32 bh)
// ---------------------------------------------------------------------------
__global__ __launch_bounds__(256, 2) void score_tf32p(
    const float* __restrict__ Q,
    const float* __restrict__ Kmat,
    const int* __restrict__ x,
    float* __restrict__ attn, int l, float scale)
{
    __shared__ float As[3][128][20];
    __shared__ float Bs[3][64][20];    // [n][k], pad->20

    int tid  = threadIdx.x;
    int lane = tid & 31, warp = tid >> 5;
    int g    = lane >> 2, tig = lane & 3;
    int wm   = (warp & 3) * 32;
    int wn   = (warp >> 2) * 32;
    int zz = blockIdx.z;
    int b = zz >> 3, hh = zz & 7;
    int m0 = blockIdx.y * 128, n0 = blockIdx.x * 64;

    const float* Abase = Q    + (size_t)b*SS*DD + hh*DKV;
    const float* Bbase = Kmat + (size_t)b*SS*DD + hh*DKV;
    float* out = attn + (((size_t)b*LL + l)*HH + hh) * (size_t)(SS*SS);

    int arow = tid >> 1, acol = (tid & 1) * 8;
    int srow = tid >> 2, scol = (tid & 3) * 4;     // 64 rows x 16 k, 16B/thread

    const float* Aptr = Abase + (size_t)(m0 + arow) * DD + acol;
    const float* Bptr = Bbase + (size_t)(n0 + srow) * DD + scol;

    float acc[2][4][4];
#pragma unroll
    for (int mi = 0; mi < 2; mi++)
#pragma unroll
        for (int ni = 0; ni < 4; ni++)
#pragma unroll
            for (int r = 0; r < 4; r++) acc[mi][ni][r] = 0.f;

    const int nk = DKV >> 4; // 4

#pragma unroll
    for (int s = 0; s < 2; s++) {
        int k0 = s * 16;
        cp16(&As[s][arow][acol],     Aptr + k0);
        cp16(&As[s][arow][acol + 4], Aptr + k0 + 4);
        cp16(&Bs[s][srow][scol],     Bptr + k0);
        CP_COMMIT();
    }

#pragma unroll
    for (int it = 0; it < nk; it++) {
        if (it + 1 < nk) CP_WAIT1(); else CP_WAIT0();
        __syncthreads();
        int s = it % 3;
#pragma unroll
        for (int kk = 0; kk < 16; kk += 8) {
            uint32_t af[2][4], bf[4][2];
#pragma unroll
            for (int mi = 0; mi < 2; mi++) {
                int r = wm + mi*16 + g;
                af[mi][0] = tf32u(As[s][r    ][kk+tig  ]);
                af[mi][1] = tf32u(As[s][r + 8][kk+tig  ]);
                af[mi][2] = tf32u(As[s][r    ][kk+tig+4]);
                af[mi][3] = tf32u(As[s][r + 8][kk+tig+4]);
            }
#pragma unroll
            for (int ni = 0; ni < 4; ni++) {
                int cc = wn + ni*8 + g;
                bf[ni][0] = tf32u(Bs[s][cc][kk+tig  ]);
                bf[ni][1] = tf32u(Bs[s][cc][kk+tig+4]);
            }
#pragma unroll
            for (int mi = 0; mi < 2; mi++)
#pragma unroll
                for (int ni = 0; ni < 4; ni++)
                    mma_tf32(acc[mi][ni], af[mi], bf[ni]);
        }
        int nx = it + 2;
        if (nx < nk) {
            int sn = nx % 3;
            int k0 = nx * 16;
            cp16(&As[sn][arow][acol],     Aptr + k0);
            cp16(&As[sn][arow][acol + 4], Aptr + k0 + 4);
            cp16(&Bs[sn][srow][scol],     Bptr + k0);
            CP_COMMIT();
        }
        __syncthreads();
    }

    const int* xb = x + b*SS;
#pragma unroll
    for (int mi = 0; mi < 2; mi++) {
        int row0 = m0 + wm + mi*16 + g;
#pragma unroll
        for (int ni = 0; ni < 4; ni++) {
            int col = n0 + wn + ni*8 + 2*tig;
            bool msk0 = (xb[col]   == 0);
            bool msk1 = (xb[col+1] == 0);
            float v0 = msk0 ? -1e9f : acc[mi][ni][0] * scale;
            float v1 = msk1 ? -1e9f : acc[mi][ni][1] * scale;
            float v2 = msk0 ? -1e9f : acc[mi][ni][2] * scale;
            float v3 = msk1 ? -1e9f : acc[mi][ni][3] * scale;
            *reinterpret_cast<float2*>(out + (size_t)row0 * SS + col)     = make_float2(v0, v1);
            *reinterpret_cast<float2*>(out + (size_t)(row0+8) * SS + col) = make_float2(v2, v3);
        }
    }
}

// ---------------------------------------------------------------------------
// Pipelined TF32 ctx GEMM: per (b,h) C[512,64] = P[512,512] @ V[512,64]
// grid (4 mtile, 32 bh)
// ---------------------------------------------------------------------------
__global__ __launch_bounds__(256, 2) void ctx_tf32p(
    const float* __restrict__ attn,
    const float* __restrict__ V,
    float* __restrict__ C, int l)
{
    __shared__ float As[3][128][20];
    __shared__ float Bs[3][16][72];

    int tid  = threadIdx.x;
    int lane = tid & 31, warp = tid >> 5;
    int g    = lane >> 2, tig = lane & 3;
    int wm   = (warp & 3) * 32;
    int wn   = (warp >> 2) * 32;
    int zz = blockIdx.y;
    int b = zz >> 3, hh = zz & 7;
    int m0 = blockIdx.x * 128;

    const float* Abase = attn + (((size_t)b*LL + l)*HH + hh) * (size_t)(SS*SS);
    const float* Bbase = V + (size_t)b*SS*DD + hh*DKV;
    float* Cb = C + (size_t)b*SS*DD + hh*DKV;

    int arow = tid >> 1, acol = (tid & 1) * 8;
    int brow = tid >> 4, bcol4 = (tid & 15) * 4;   // 16 rows x 64 n: 16B/thread

    const float* Aptr = Abase + (size_t)(m0 + arow) * SS + acol;
    const float* Bptr = Bbase + (size_t)brow * DD + bcol4;

    float acc[2][4][4];
#pragma unroll
    for (int mi = 0; mi < 2; mi++)
#pragma unroll
        for (int ni = 0; ni < 4; ni++)
#pragma unroll
            for (int r = 0; r < 4; r++) acc[mi][ni][r] = 0.f;

    const int nk = SS >> 4; // 32

#pragma unroll
    for (int s = 0; s < 2; s++) {
        int k0 = s * 16;
        cp16(&As[s][arow][acol],     Aptr + k0);
        cp16(&As[s][arow][acol + 4], Aptr + k0 + 4);
        cp16(&Bs[s][brow][bcol4],    Bptr + (size_t)k0 * DD);
        CP_COMMIT();
    }

    for (int it = 0; it < nk; it++) {
        if (it + 1 < nk) CP_WAIT1(); else CP_WAIT0();
        __syncthreads();
        int s = it % 3;
#pragma unroll
        for (int kk = 0; kk < 16; kk += 8) {
            uint32_t af[2][4], bf[4][2];
#pragma unroll
            for (int mi = 0; mi < 2; mi++) {
                int r = wm + mi*16 + g;
                af[mi][0] = tf32u(As[s][r    ][kk+tig  ]);
                af[mi][1] = tf32u(As[s][r + 8][kk+tig  ]);
                af[mi][2] = tf32u(As[s][r    ][kk+tig+4]);
                af[mi][3] = tf32u(As[s][r + 8][kk+tig+4]);
            }
#pragma unroll
            for (int ni = 0; ni < 4; ni++) {
                int cc = wn + ni*8 + g;
                bf[ni][0] = tf32u(Bs[s][kk+tig  ][cc]);
                bf[ni][1] = tf32u(Bs[s][kk+tig+4][cc]);
            }
#pragma unroll
            for (int mi = 0; mi < 2; mi++)
#pragma unroll
                for (int ni = 0; ni < 4; ni++)
                    mma_tf32(acc[mi][ni], af[mi], bf[ni]);
        }
        int nx = it + 2;
        if (nx < nk) {
            int sn = nx % 3;
            int k0 = nx * 16;
            cp16(&As[sn][arow][acol],     Aptr + k0);
            cp16(&As[sn][arow][acol + 4], Aptr + k0 + 4);
            cp16(&Bs[sn][brow][bcol4],    Bptr + (size_t)k0 * DD);
            CP_COMMIT();
        }
        __syncthreads();
    }

#pragma unroll
    for (int mi = 0; mi < 2; mi++) {
        int row0 = m0 + wm + mi*16 + g;
#pragma unroll
        for (int ni = 0; ni < 4; ni++) {
            int col = wn + ni*8 + 2*tig;
            *reinterpret_cast<float2*>(Cb + (size_t)row0 * DD + col)
                = make_float2(acc[mi][ni][0], acc[mi][ni][1]);
            *reinterpret_cast<float2*>(Cb + (size_t)(row0+8) * DD + col)
                = make_float2(acc[mi][ni][2], acc[mi][ni][3]);
        }
    }
}

// ---------------------------------------------------------------------------
__global__ __launch_bounds__(128) void softmax_kernel(float* __restrict__ attn, int l)
{
    __shared__ float red[8];
    int row = blockIdx.x;
    int b = row >> 12;
    int rem = row & 4095;
    float* p = attn + (size_t)b*(LL*HH*SS*SS) + (size_t)l*(HH*SS*SS) + (size_t)rem*SS;
    int t = threadIdx.x;
    int lane = t & 31, wid = t >> 5;

    float v[4];
#pragma unroll
    for (int i = 0; i < 4; i++) v[i] = p[t + 128*i];

    float mx = fmaxf(fmaxf(v[0],v[1]), fmaxf(v[2],v[3]));
#pragma unroll
    for (int o = 16; o > 0; o >>= 1) mx = fmaxf(mx, __shfl_xor_sync(0xffffffffu, mx, o));
    if (lane == 0) red[wid] = mx;
    __syncthreads();
    mx = fmaxf(fmaxf(red[0],red[1]), fmaxf(red[2],red[3]));

    float s = 0.f;
#pragma unroll
    for (int i = 0; i < 4; i++) { v[i] = __expf(v[i] - mx); s += v[i]; }
#pragma unroll
    for (int o = 16; o > 0; o >>= 1) s += __shfl_xor_sync(0xffffffffu, s, o);
    if (lane == 0) red[4 + wid] = s;
    __syncthreads();
    s = red[4] + red[5] + red[6] + red[7];
    float inv = 1.0f / s;
#pragma unroll
    for (int i = 0; i < 4; i++) p[t + 128*i] = v[i] * inv;
}

// ---------------------------------------------------------------------------
__global__ __launch_bounds__(128) void ln_kernel(
    const float* __restrict__ in,
    const float* __restrict__ g,
    const float* __restrict__ bta,
    float* __restrict__ out)
{
    __shared__ float red[8];
    int row = blockIdx.x;
    const float* p = in + (size_t)row*DD;
    float* o = out + (size_t)row*DD;
    int t = threadIdx.x;
    int lane = t & 31, wid = t >> 5;

    float v[4];
    float s = 0.f, sq = 0.f;
#pragma unroll
    for (int i = 0; i < 4; i++) { v[i] = p[t + 128*i]; s += v[i]; sq += v[i]*v[i]; }
#pragma unroll
    for (int o2 = 16; o2 > 0; o2 >>= 1) {
        s  += __shfl_xor_sync(0xffffffffu, s,  o2);
        sq += __shfl_xor_sync(0xffffffffu, sq, o2);
    }
    if (lane == 0) { red[wid] = s; red[4+wid] = sq; }
    __syncthreads();
    s  = red[0]+red[1]+red[2]+red[3];
    sq = red[4]+red[5]+red[6]+red[7];
    float mu = s * (1.0f/DD);
    float var = sq * (1.0f/DD) - mu*mu;
    float rstd = rsqrtf(var + EPS);
#pragma unroll
    for (int i = 0; i < 4; i++) {
        int col = t + 128*i;
        o[col] = (v[i] - mu) * rstd * g[col] + bta[col];
    }
}

// ---------------------------------------------------------------------------
extern "C" void kernel_launch(void* const* d_in, const int* in_sizes, int n_in,
                              void* d_out, int out_size)
{
    const int*   x    = (const int*)  d_in[0];
    const float* emb  = (const float*)d_in[1];
    const float* pe   = (const float*)d_in[2];
    const float* WQ   = (const float*)d_in[3];
    const float* bQ   = (const float*)d_in[4];
    const float* WK   = (const float*)d_in[5];
    const float* bK   = (const float*)d_in[6];
    const float* WV   = (const float*)d_in[7];
    const float* bV   = (const float*)d_in[8];
    const float* WO   = (const float*)d_in[9];
    const float* bO   = (const float*)d_in[10];
    const float* ln1g = (const float*)d_in[11];
    const float* ln1b = (const float*)d_in[12];
    const float* W1   = (const float*)d_in[13];
    const float* b1   = (const float*)d_in[14];
    const float* W2   = (const float*)d_in[15];
    const float* b2   = (const float*)d_in[16];
    const float* ln2g = (const float*)d_in[17];
    const float* ln2b = (const float*)d_in[18];

    float* out  = (float*)d_out;
    float* attn = out + (size_t)NTOK*DD;

    float *h, *q, *k, *v, *ctx, *tmp, *ff;
    cudaGetSymbolAddress((void**)&h,   g_h);
    cudaGetSymbolAddress((void**)&q,   g_q);
    cudaGetSymbolAddress((void**)&k,   g_k);
    cudaGetSymbolAddress((void**)&v,   g_v);
    cudaGetSymbolAddress((void**)&ctx, g_ctx);
    cudaGetSymbolAddress((void**)&tmp, g_tmp);
    cudaGetSymbolAddress((void**)&ff,  g_ff);

    const float scale = 0.125f;

    embed_kernel<<<NTOK, 128>>>(x, emb, pe, h);

    for (int l = 0; l < LL; l++) {
        const float* wq = WQ + (size_t)l*DD*DD;
        const float* wk = WK + (size_t)l*DD*DD;
        const float* wv = WV + (size_t)l*DD*DD;
        const float* wo = WO + (size_t)l*DD*DD;
        const float* w1 = W1 + (size_t)l*DD*DFF;
        const float* w2 = W2 + (size_t)l*DFF*DD;

        gemm_tf32p<<<dim3(8,16,3), 256>>>(h, DD,
            wq, wk, wv, DD,
            bQ + l*DD, bK + l*DD, bV + l*DD,
            nullptr,
            q, k, v, DD, DD, 0);

        score_tf32p<<<dim3(8,4,32), 256>>>(q, k, x, attn, l, scale);
        softmax_kernel<<<BB*HH*SS, 128>>>(attn, l);
        ctx_tf32p<<<dim3(4,32), 256>>>(attn, v, ctx, l);

        gemm_tf32p<<<dim3(8,16,1), 256>>>(ctx, DD,
            wo, wo, wo, DD,
            bO + l*DD, bO + l*DD, bO + l*DD,
            h,
            tmp, tmp, tmp, DD, DD, 0);
        ln_kernel<<<NTOK, 128>>>(tmp, ln1g + l*DD, ln1b + l*DD, h);

        gemm_tf32p<<<dim3(32,16,1), 256>>>(h, DD,
            w1, w1, w1, DFF,
            b1 + l*DFF, b1 + l*DFF, b1 + l*DFF,
            nullptr,
            ff, ff, ff, DFF, DD, 1);

        gemm_tf32p<<<dim3(8,16,1), 256>>>(ff, DFF,
            w2, w2, w2, DD,
            b2 + l*DD, b2 + l*DD, b2 + l*DD,
            h,
            tmp, tmp, tmp, DD, DFF, 0);

        float* lnout = (l == LL-1) ? out : h;
        ln_kernel<<<NTOK, 128>>>(tmp, ln2g + l*DD, ln2b + l*DD, lnout);
    }
}

// round 7
// speedup vs baseline: 4.7790x; 1.0961x over previous
#include <cuda_runtime.h>
#include <cuda_bf16.h>
#include <math.h>
#include <stdint.h>

// Problem constants
#define BB 4
#define SS 512
#define DD 512
#define HH 8
#define DKV 64
#define DFF 2048
#define LL 6
#define NTOK (BB*SS)          // 2048
#define EPS 1e-5f

// Scratch (device globals; no allocation allowed)
__device__ __align__(128) float g_h[NTOK*DD];
__device__ __align__(128) float g_q[NTOK*DD];
__device__ __align__(128) float g_k[NTOK*DD];
__device__ __align__(128) float g_v[NTOK*DD];
__device__ __align__(128) float g_ctx[NTOK*DD];
__device__ __align__(128) float g_tmp[NTOK*DD];
__device__ __align__(128) float g_ff[NTOK*DFF];

// ---------------------------------------------------------------------------
__global__ void embed_kernel(const int* __restrict__ x,
                             const float* __restrict__ emb,
                             const float* __restrict__ pe,
                             float* __restrict__ h)
{
    int tok = blockIdx.x;
    int s = tok & (SS-1);
    int id = x[tok];
    int t = threadIdx.x; // 0..127
    const float4* e4 = reinterpret_cast<const float4*>(emb + (size_t)id*DD);
    const float4* p4 = reinterpret_cast<const float4*>(pe + (size_t)s*DD);
    float4 ev = e4[t], pv = p4[t];
    float4 r; r.x=ev.x+pv.x; r.y=ev.y+pv.y; r.z=ev.z+pv.z; r.w=ev.w+pv.w;
    reinterpret_cast<float4*>(h + (size_t)tok*DD)[t] = r;
}

__device__ __forceinline__ float gelu_f(float x) {
    return 0.5f * x * (1.0f + tanhf(0.7978845608028654f * (x + 0.044715f*x*x*x)));
}

__device__ __forceinline__ uint32_t tf32u(float x) {
    uint32_t u;
    asm("cvt.rna.tf32.f32 %0, %1;" : "=r"(u) : "f"(x));
    return u;
}

__device__ __forceinline__ void mma_tf32(float* c, const uint32_t* a, const uint32_t* b) {
    asm volatile(
        "mma.sync.aligned.m16n8k8.row.col.f32.tf32.tf32.f32 "
        "{%0,%1,%2,%3}, {%4,%5,%6,%7}, {%8,%9}, {%0,%1,%2,%3};"
        : "+f"(c[0]), "+f"(c[1]), "+f"(c[2]), "+f"(c[3])
        : "r"(a[0]), "r"(a[1]), "r"(a[2]), "r"(a[3]), "r"(b[0]), "r"(b[1]));
}

__device__ __forceinline__ void cp16(void* smem_dst, const void* gsrc) {
    uint32_t s = (uint32_t)__cvta_generic_to_shared(smem_dst);
    asm volatile("cp.async.cg.shared.global [%0], [%1], 16;" :: "r"(s), "l"(gsrc));
}
#define CP_COMMIT() asm volatile("cp.async.commit_group;")
#define CP_WAIT2()  asm volatile("cp.async.wait_group 2;")
#define CP_WAIT1()  asm volatile("cp.async.wait_group 1;")
#define CP_WAIT0()  asm volatile("cp.async.wait_group 0;")

// smem layout sizes (floats)
#define A_TILE_F (128*20)          // [128][20]
#define B_TILE_F(BN) (16*((BN)+8)) // [16][BN+8]

// ---------------------------------------------------------------------------
// Pipelined TF32 GEMM: C[M,N] = A[M,K] @ B[K,N] (+bias)(+res)(+gelu)
// CTA tile 128(M) x BN(N), BK=16, 4-stage cp.async, single sync per iter.
// 256 threads. BN=128: warps 2m x 4n (warp 64x32). BN=64: 4m x 2n (32x32).
// blockIdx.z selects (B,bias,C) triple. grid: (N/BN, M/128, nz)
// ---------------------------------------------------------------------------
template<int BN, int WR>
__global__ __launch_bounds__(256, 2) void gemm_tf32p(
    const float* __restrict__ A, int lda,
    const float* __restrict__ B0, const float* __restrict__ B1, const float* __restrict__ B2,
    int ldb,
    const float* __restrict__ bias0, const float* __restrict__ bias1, const float* __restrict__ bias2,
    const float* __restrict__ res,
    float* __restrict__ C0, float* __restrict__ C1, float* __restrict__ C2,
    int ldc, int K, int act)
{
    constexpr int MI = 128/(WR*16);
    constexpr int WC = 8/WR;
    constexpr int NI = BN/(WC*8);

    int z = blockIdx.z;
    const float* B    = (z == 0) ? B0    : ((z == 1) ? B1    : B2);
    const float* bias = (z == 0) ? bias0 : ((z == 1) ? bias1 : bias2);
    float*       C    = (z == 0) ? C0    : ((z == 1) ? C1    : C2);

    extern __shared__ float dsm[];
    float (*As)[128][20]  = reinterpret_cast<float(*)[128][20]>(dsm);
    float (*Bs)[16][BN+8] = reinterpret_cast<float(*)[16][BN+8]>(dsm + 4*A_TILE_F);

    int tid  = threadIdx.x;
    int lane = tid & 31, warp = tid >> 5;
    int g    = lane >> 2, tig = lane & 3;
    int mw   = warp % WR, nw = warp / WR;
    int wm   = mw * (MI*16);
    int wn   = nw * (NI*8);
    int m0   = blockIdx.y * 128, n0 = blockIdx.x * BN;

    // loaders
    int arow = tid >> 1, acol = (tid & 1) * 8;     // 128 x 16, 2 cp16/thread
    int brow = tid >> 4;                            // 16 rows
    int bcol = (BN == 64) ? (tid & 15) * 4 : (tid & 15) * 8;

    const float* Aptr = A + (size_t)(m0 + arow) * lda + acol;
    const float* Bptr = B + (size_t)brow * ldb + n0 + bcol;

    float acc[MI][NI][4];
#pragma unroll
    for (int mi = 0; mi < MI; mi++)
#pragma unroll
        for (int ni = 0; ni < NI; ni++)
#pragma unroll
            for (int r = 0; r < 4; r++) acc[mi][ni][r] = 0.f;

    int nk = K >> 4;

#pragma unroll
    for (int s = 0; s < 3; s++) {
        int k0 = s * 16;
        cp16(&As[s][arow][acol],     Aptr + k0);
        cp16(&As[s][arow][acol + 4], Aptr + k0 + 4);
        cp16(&Bs[s][brow][bcol],     Bptr + (size_t)k0 * ldb);
        if (BN == 128)
            cp16(&Bs[s][brow][bcol + 4], Bptr + (size_t)k0 * ldb + 4);
        CP_COMMIT();
    }

    for (int it = 0; it < nk; it++) {
        if (it + 2 < nk) CP_WAIT2();
        else if (it + 1 < nk) CP_WAIT1();
        else CP_WAIT0();
        __syncthreads();
        int s = it & 3;
#pragma unroll
        for (int kk = 0; kk < 16; kk += 8) {
            uint32_t af[MI][4], bf[NI][2];
#pragma unroll
            for (int mi = 0; mi < MI; mi++) {
                int r = wm + mi*16 + g;
                af[mi][0] = tf32u(As[s][r    ][kk+tig  ]);
                af[mi][1] = tf32u(As[s][r + 8][kk+tig  ]);
                af[mi][2] = tf32u(As[s][r    ][kk+tig+4]);
                af[mi][3] = tf32u(As[s][r + 8][kk+tig+4]);
            }
#pragma unroll
            for (int ni = 0; ni < NI; ni++) {
                int cc = wn + ni*8 + g;
                bf[ni][0] = tf32u(Bs[s][kk+tig  ][cc]);
                bf[ni][1] = tf32u(Bs[s][kk+tig+4][cc]);
            }
#pragma unroll
            for (int mi = 0; mi < MI; mi++)
#pragma unroll
                for (int ni = 0; ni < NI; ni++)
                    mma_tf32(acc[mi][ni], af[mi], bf[ni]);
        }
        int nx = it + 3;
        if (nx < nk) {
            int sn = nx & 3;
            int k0 = nx * 16;
            cp16(&As[sn][arow][acol],     Aptr + k0);
            cp16(&As[sn][arow][acol + 4], Aptr + k0 + 4);
            cp16(&Bs[sn][brow][bcol],     Bptr + (size_t)k0 * ldb);
            if (BN == 128)
                cp16(&Bs[sn][brow][bcol + 4], Bptr + (size_t)k0 * ldb + 4);
            CP_COMMIT();
        }
    }

#pragma unroll
    for (int mi = 0; mi < MI; mi++) {
        int row0 = m0 + wm + mi*16 + g;
#pragma unroll
        for (int ni = 0; ni < NI; ni++) {
            int col = n0 + wn + ni*8 + 2*tig;
            float b0 = 0.f, b1 = 0.f;
            if (bias) { b0 = bias[col]; b1 = bias[col+1]; }
            float v0 = acc[mi][ni][0] + b0;
            float v1 = acc[mi][ni][1] + b1;
            float v2 = acc[mi][ni][2] + b0;
            float v3 = acc[mi][ni][3] + b1;
            if (res) {
                const float* r0p = res + (size_t)row0 * ldc + col;
                const float* r1p = res + (size_t)(row0+8) * ldc + col;
                v0 += r0p[0]; v1 += r0p[1];
                v2 += r1p[0]; v3 += r1p[1];
            }
            if (act) {
                v0 = gelu_f(v0); v1 = gelu_f(v1);
                v2 = gelu_f(v2); v3 = gelu_f(v3);
            }
            *reinterpret_cast<float2*>(C + (size_t)row0 * ldc + col)     = make_float2(v0, v1);
            *reinterpret_cast<float2*>(C + (size_t)(row0+8) * ldc + col) = make_float2(v2, v3);
        }
    }
}

// ---------------------------------------------------------------------------
// Pipelined TF32 score GEMM: per (b,h) S = Q @ K^T * scale + mask
// CTA 128(M) x 128(N kv rows), K=64. B smem [n][k]. 4-stage, 1 sync/iter.
// warps 2m x 4n (warp 64x32). grid (4 ntile, 4 mtile, 32 bh)
// ---------------------------------------------------------------------------
__global__ __launch_bounds__(256, 2) void score_tf32p(
    const float* __restrict__ Q,
    const float* __restrict__ Kmat,
    const int* __restrict__ x,
    float* __restrict__ attn, int l, float scale)
{
    constexpr int MI = 4, NI = 4;

    extern __shared__ float dsm[];
    float (*As)[128][20] = reinterpret_cast<float(*)[128][20]>(dsm);
    float (*Bs)[128][20] = reinterpret_cast<float(*)[128][20]>(dsm + 4*A_TILE_F);

    int tid  = threadIdx.x;
    int lane = tid & 31, warp = tid >> 5;
    int g    = lane >> 2, tig = lane & 3;
    int mw   = warp & 1, nw = warp >> 1;
    int wm   = mw * 64;
    int wn   = nw * 32;
    int zz = blockIdx.z;
    int b = zz >> 3, hh = zz & 7;
    int m0 = blockIdx.y * 128, n0 = blockIdx.x * 128;

    const float* Abase = Q    + (size_t)b*SS*DD + hh*DKV;
    const float* Bbase = Kmat + (size_t)b*SS*DD + hh*DKV;
    float* out = attn + (((size_t)b*LL + l)*HH + hh) * (size_t)(SS*SS);

    int arow = tid >> 1, acol = (tid & 1) * 8;   // both operands: 128 rows x 16 k

    const float* Aptr = Abase + (size_t)(m0 + arow) * DD + acol;
    const float* Bptr = Bbase + (size_t)(n0 + arow) * DD + acol;

    float acc[MI][NI][4];
#pragma unroll
    for (int mi = 0; mi < MI; mi++)
#pragma unroll
        for (int ni = 0; ni < NI; ni++)
#pragma unroll
            for (int r = 0; r < 4; r++) acc[mi][ni][r] = 0.f;

    const int nk = DKV >> 4; // 4

#pragma unroll
    for (int s = 0; s < 3; s++) {
        int k0 = s * 16;
        cp16(&As[s][arow][acol],     Aptr + k0);
        cp16(&As[s][arow][acol + 4], Aptr + k0 + 4);
        cp16(&Bs[s][arow][acol],     Bptr + k0);
        cp16(&Bs[s][arow][acol + 4], Bptr + k0 + 4);
        CP_COMMIT();
    }

#pragma unroll
    for (int it = 0; it < nk; it++) {
        if (it + 2 < nk) CP_WAIT2();
        else if (it + 1 < nk) CP_WAIT1();
        else CP_WAIT0();
        __syncthreads();
        int s = it & 3;
#pragma unroll
        for (int kk = 0; kk < 16; kk += 8) {
            uint32_t af[MI][4], bf[NI][2];
#pragma unroll
            for (int mi = 0; mi < MI; mi++) {
                int r = wm + mi*16 + g;
                af[mi][0] = tf32u(As[s][r    ][kk+tig  ]);
                af[mi][1] = tf32u(As[s][r + 8][kk+tig  ]);
                af[mi][2] = tf32u(As[s][r    ][kk+tig+4]);
                af[mi][3] = tf32u(As[s][r + 8][kk+tig+4]);
            }
#pragma unroll
            for (int ni = 0; ni < NI; ni++) {
                int cc = wn + ni*8 + g;
                bf[ni][0] = tf32u(Bs[s][cc][kk+tig  ]);
                bf[ni][1] = tf32u(Bs[s][cc][kk+tig+4]);
            }
#pragma unroll
            for (int mi = 0; mi < MI; mi++)
#pragma unroll
                for (int ni = 0; ni < NI; ni++)
                    mma_tf32(acc[mi][ni], af[mi], bf[ni]);
        }
        int nx = it + 3;
        if (nx < nk) {
            int sn = nx & 3;
            int k0 = nx * 16;
            cp16(&As[sn][arow][acol],     Aptr + k0);
            cp16(&As[sn][arow][acol + 4], Aptr + k0 + 4);
            cp16(&Bs[sn][arow][acol],     Bptr + k0);
            cp16(&Bs[sn][arow][acol + 4], Bptr + k0 + 4);
            CP_COMMIT();
        }
    }

    const int* xb = x + b*SS;
#pragma unroll
    for (int mi = 0; mi < MI; mi++) {
        int row0 = m0 + wm + mi*16 + g;
#pragma unroll
        for (int ni = 0; ni < NI; ni++) {
            int col = n0 + wn + ni*8 + 2*tig;
            bool msk0 = (xb[col]   == 0);
            bool msk1 = (xb[col+1] == 0);
            float v0 = msk0 ? -1e9f : acc[mi][ni][0] * scale;
            float v1 = msk1 ? -1e9f : acc[mi][ni][1] * scale;
            float v2 = msk0 ? -1e9f : acc[mi][ni][2] * scale;
            float v3 = msk1 ? -1e9f : acc[mi][ni][3] * scale;
            *reinterpret_cast<float2*>(out + (size_t)row0 * SS + col)     = make_float2(v0, v1);
            *reinterpret_cast<float2*>(out + (size_t)(row0+8) * SS + col) = make_float2(v2, v3);
        }
    }
}

// ---------------------------------------------------------------------------
// Pipelined TF32 ctx GEMM: per (b,h) C[512,64] = P[512,512] @ V[512,64]
// CTA 128x64, 4-stage, 1 sync/iter. warps 4m x 2n. grid (4 mtile, 32 bh)
// ---------------------------------------------------------------------------
__global__ __launch_bounds__(256, 2) void ctx_tf32p(
    const float* __restrict__ attn,
    const float* __restrict__ V,
    float* __restrict__ C, int l)
{
    constexpr int MI = 2, NI = 4;

    extern __shared__ float dsm[];
    float (*As)[128][20] = reinterpret_cast<float(*)[128][20]>(dsm);
    float (*Bs)[16][72]  = reinterpret_cast<float(*)[16][72]>(dsm + 4*A_TILE_F);

    int tid  = threadIdx.x;
    int lane = tid & 31, warp = tid >> 5;
    int g    = lane >> 2, tig = lane & 3;
    int wm   = (warp & 3) * 32;
    int wn   = (warp >> 2) * 32;
    int zz = blockIdx.y;
    int b = zz >> 3, hh = zz & 7;
    int m0 = blockIdx.x * 128;

    const float* Abase = attn + (((size_t)b*LL + l)*HH + hh) * (size_t)(SS*SS);
    const float* Bbase = V + (size_t)b*SS*DD + hh*DKV;
    float* Cb = C + (size_t)b*SS*DD + hh*DKV;

    int arow = tid >> 1, acol = (tid & 1) * 8;
    int brow = tid >> 4, bcol = (tid & 15) * 4;

    const float* Aptr = Abase + (size_t)(m0 + arow) * SS + acol;
    const float* Bptr = Bbase + (size_t)brow * DD + bcol;

    float acc[MI][NI][4];
#pragma unroll
    for (int mi = 0; mi < MI; mi++)
#pragma unroll
        for (int ni = 0; ni < NI; ni++)
#pragma unroll
            for (int r = 0; r < 4; r++) acc[mi][ni][r] = 0.f;

    const int nk = SS >> 4; // 32

#pragma unroll
    for (int s = 0; s < 3; s++) {
        int k0 = s * 16;
        cp16(&As[s][arow][acol],     Aptr + k0);
        cp16(&As[s][arow][acol + 4], Aptr + k0 + 4);
        cp16(&Bs[s][brow][bcol],     Bptr + (size_t)k0 * DD);
        CP_COMMIT();
    }

    for (int it = 0; it < nk; it++) {
        if (it + 2 < nk) CP_WAIT2();
        else if (it + 1 < nk) CP_WAIT1();
        else CP_WAIT0();
        __syncthreads();
        int s = it & 3;
#pragma unroll
        for (int kk = 0; kk < 16; kk += 8) {
            uint32_t af[MI][4], bf[NI][2];
#pragma unroll
            for (int mi = 0; mi < MI; mi++) {
                int r = wm + mi*16 + g;
                af[mi][0] = tf32u(As[s][r    ][kk+tig  ]);
                af[mi][1] = tf32u(As[s][r + 8][kk+tig  ]);
                af[mi][2] = tf32u(As[s][r    ][kk+tig+4]);
                af[mi][3] = tf32u(As[s][r + 8][kk+tig+4]);
            }
#pragma unroll
            for (int ni = 0; ni < NI; ni++) {
                int cc = wn + ni*8 + g;
                bf[ni][0] = tf32u(Bs[s][kk+tig  ][cc]);
                bf[ni][1] = tf32u(Bs[s][kk+tig+4][cc]);
            }
#pragma unroll
            for (int mi = 0; mi < MI; mi++)
#pragma unroll
                for (int ni = 0; ni < NI; ni++)
                    mma_tf32(acc[mi][ni], af[mi], bf[ni]);
        }
        int nx = it + 3;
        if (nx < nk) {
            int sn = nx & 3;
            int k0 = nx * 16;
            cp16(&As[sn][arow][acol],     Aptr + k0);
            cp16(&As[sn][arow][acol + 4], Aptr + k0 + 4);
            cp16(&Bs[sn][brow][bcol],     Bptr + (size_t)k0 * DD);
            CP_COMMIT();
        }
    }

#pragma unroll
    for (int mi = 0; mi < MI; mi++) {
        int row0 = m0 + wm + mi*16 + g;
#pragma unroll
        for (int ni = 0; ni < NI; ni++) {
            int col = wn + ni*8 + 2*tig;
            *reinterpret_cast<float2*>(Cb + (size_t)row0 * DD + col)
                = make_float2(acc[mi][ni][0], acc[mi][ni][1]);
            *reinterpret_cast<float2*>(Cb + (size_t)(row0+8) * DD + col)
                = make_float2(acc[mi][ni][2], acc[mi][ni][3]);
        }
    }
}

// ---------------------------------------------------------------------------
__global__ __launch_bounds__(128) void softmax_kernel(float* __restrict__ attn, int l)
{
    __shared__ float red[8];
    int row = blockIdx.x;
    int b = row >> 12;
    int rem = row & 4095;
    float* p = attn + (size_t)b*(LL*HH*SS*SS) + (size_t)l*(HH*SS*SS) + (size_t)rem*SS;
    int t = threadIdx.x;
    int lane = t & 31, wid = t >> 5;

    float v[4];
#pragma unroll
    for (int i = 0; i < 4; i++) v[i] = p[t + 128*i];

    float mx = fmaxf(fmaxf(v[0],v[1]), fmaxf(v[2],v[3]));
#pragma unroll
    for (int o = 16; o > 0; o >>= 1) mx = fmaxf(mx, __shfl_xor_sync(0xffffffffu, mx, o));
    if (lane == 0) red[wid] = mx;
    __syncthreads();
    mx = fmaxf(fmaxf(red[0],red[1]), fmaxf(red[2],red[3]));

    float s = 0.f;
#pragma unroll
    for (int i = 0; i < 4; i++) { v[i] = __expf(v[i] - mx); s += v[i]; }
#pragma unroll
    for (int o = 16; o > 0; o >>= 1) s += __shfl_xor_sync(0xffffffffu, s, o);
    if (lane == 0) red[4 + wid] = s;
    __syncthreads();
    s = red[4] + red[5] + red[6] + red[7];
    float inv = 1.0f / s;
#pragma unroll
    for (int i = 0; i < 4; i++) p[t + 128*i] = v[i] * inv;
}

// ---------------------------------------------------------------------------
__global__ __launch_bounds__(128) void ln_kernel(
    const float* __restrict__ in,
    const float* __restrict__ g,
    const float* __restrict__ bta,
    float* __restrict__ out)
{
    __shared__ float red[8];
    int row = blockIdx.x;
    const float* p = in + (size_t)row*DD;
    float* o = out + (size_t)row*DD;
    int t = threadIdx.x;
    int lane = t & 31, wid = t >> 5;

    float v[4];
    float s = 0.f, sq = 0.f;
#pragma unroll
    for (int i = 0; i < 4; i++) { v[i] = p[t + 128*i]; s += v[i]; sq += v[i]*v[i]; }
#pragma unroll
    for (int o2 = 16; o2 > 0; o2 >>= 1) {
        s  += __shfl_xor_sync(0xffffffffu, s,  o2);
        sq += __shfl_xor_sync(0xffffffffu, sq, o2);
    }
    if (lane == 0) { red[wid] = s; red[4+wid] = sq; }
    __syncthreads();
    s  = red[0]+red[1]+red[2]+red[3];
    sq = red[4]+red[5]+red[6]+red[7];
    float mu = s * (1.0f/DD);
    float var = sq * (1.0f/DD) - mu*mu;
    float rstd = rsqrtf(var + EPS);
#pragma unroll
    for (int i = 0; i < 4; i++) {
        int col = t + 128*i;
        o[col] = (v[i] - mu) * rstd * g[col] + bta[col];
    }
}

// ---------------------------------------------------------------------------
extern "C" void kernel_launch(void* const* d_in, const int* in_sizes, int n_in,
                              void* d_out, int out_size)
{
    const int*   x    = (const int*)  d_in[0];
    const float* emb  = (const float*)d_in[1];
    const float* pe   = (const float*)d_in[2];
    const float* WQ   = (const float*)d_in[3];
    const float* bQ   = (const float*)d_in[4];
    const float* WK   = (const float*)d_in[5];
    const float* bK   = (const float*)d_in[6];
    const float* WV   = (const float*)d_in[7];
    const float* bV   = (const float*)d_in[8];
    const float* WO   = (const float*)d_in[9];
    const float* bO   = (const float*)d_in[10];
    const float* ln1g = (const float*)d_in[11];
    const float* ln1b = (const float*)d_in[12];
    const float* W1   = (const float*)d_in[13];
    const float* b1   = (const float*)d_in[14];
    const float* W2   = (const float*)d_in[15];
    const float* b2   = (const float*)d_in[16];
    const float* ln2g = (const float*)d_in[17];
    const float* ln2b = (const float*)d_in[18];

    float* out  = (float*)d_out;
    float* attn = out + (size_t)NTOK*DD;

    float *h, *q, *k, *v, *ctx, *tmp, *ff;
    cudaGetSymbolAddress((void**)&h,   g_h);
    cudaGetSymbolAddress((void**)&q,   g_q);
    cudaGetSymbolAddress((void**)&k,   g_k);
    cudaGetSymbolAddress((void**)&v,   g_v);
    cudaGetSymbolAddress((void**)&ctx, g_ctx);
    cudaGetSymbolAddress((void**)&tmp, g_tmp);
    cudaGetSymbolAddress((void**)&ff,  g_ff);

    // dynamic smem sizes (bytes)
    const int SM_D128 = (4*A_TILE_F + 4*B_TILE_F(128)) * 4;  // 75776
    const int SM_D64  = (4*A_TILE_F + 4*B_TILE_F(64))  * 4;  // 59392
    const int SM_SC   = (4*A_TILE_F + 4*A_TILE_F)      * 4;  // 81920

    static int attr_done = 0;
    if (!attr_done) {
        cudaFuncSetAttribute(gemm_tf32p<128,2>, cudaFuncAttributeMaxDynamicSharedMemorySize, SM_D128);
        cudaFuncSetAttribute(gemm_tf32p<64,4>,  cudaFuncAttributeMaxDynamicSharedMemorySize, SM_D64);
        cudaFuncSetAttribute(score_tf32p,       cudaFuncAttributeMaxDynamicSharedMemorySize, SM_SC);
        cudaFuncSetAttribute(ctx_tf32p,         cudaFuncAttributeMaxDynamicSharedMemorySize, SM_D64);
        attr_done = 1;
    }

    const float scale = 0.125f;

    embed_kernel<<<NTOK, 128>>>(x, emb, pe, h);

    for (int l = 0; l < LL; l++) {
        const float* wq = WQ + (size_t)l*DD*DD;
        const float* wk = WK + (size_t)l*DD*DD;
        const float* wv = WV + (size_t)l*DD*DD;
        const float* wo = WO + (size_t)l*DD*DD;
        const float* w1 = W1 + (size_t)l*DD*DFF;
        const float* w2 = W2 + (size_t)l*DFF*DD;

        // fused QKV, 128-wide tiles: grid (512/128, 2048/128, 3) = (4,16,3)
        gemm_tf32p<128,2><<<dim3(4,16,3), 256, SM_D128>>>(h, DD,
            wq, wk, wv, DD,
            bQ + l*DD, bK + l*DD, bV + l*DD,
            nullptr,
            q, k, v, DD, DD, 0);

        score_tf32p<<<dim3(4,4,32), 256, SM_SC>>>(q, k, x, attn, l, scale);
        softmax_kernel<<<BB*HH*SS, 128>>>(attn, l);
        ctx_tf32p<<<dim3(4,32), 256, SM_D64>>>(attn, v, ctx, l);

        // WO: 64-wide tiles, grid (8,16)
        gemm_tf32p<64,4><<<dim3(8,16,1), 256, SM_D64>>>(ctx, DD,
            wo, wo, wo, DD,
            bO + l*DD, bO + l*DD, bO + l*DD,
            h,
            tmp, tmp, tmp, DD, DD, 0);
        ln_kernel<<<NTOK, 128>>>(tmp, ln1g + l*DD, ln1b + l*DD, h);

        // FFN1: 128-wide tiles, grid (2048/128, 16) = (16,16)
        gemm_tf32p<128,2><<<dim3(16,16,1), 256, SM_D128>>>(h, DD,
            w1, w1, w1, DFF,
            b1 + l*DFF, b1 + l*DFF, b1 + l*DFF,
            nullptr,
            ff, ff, ff, DFF, DD, 1);

        // FFN2: 64-wide tiles, grid (8,16)
        gemm_tf32p<64,4><<<dim3(8,16,1), 256, SM_D64>>>(ff, DFF,
            w2, w2, w2, DD,
            b2 + l*DD, b2 + l*DD, b2 + l*DD,
            h,
            tmp, tmp, tmp, DD, DFF, 0);

        float* lnout = (l == LL-1) ? out : h;
        ln_kernel<<<NTOK, 128>>>(tmp, ln2g + l*DD, ln2b + l*DD, lnout);
    }
}

// round 8
// speedup vs baseline: 5.0403x; 1.0547x over previous
#include <cuda_runtime.h>
#include <cuda_bf16.h>
#include <math.h>
#include <stdint.h>

// Problem constants
#define BB 4
#define SS 512
#define DD 512
#define HH 8
#define DKV 64
#define DFF 2048
#define LL 6
#define NTOK (BB*SS)          // 2048
#define EPS 1e-5f

// Scratch (device globals; no allocation allowed)
__device__ __align__(128) float g_h[NTOK*DD];
__device__ __align__(128) float g_q[NTOK*DD];
__device__ __align__(128) float g_k[NTOK*DD];
__device__ __align__(128) float g_v[NTOK*DD];
__device__ __align__(128) float g_ctx[NTOK*DD];
__device__ __align__(128) float g_tmp[NTOK*DD];
__device__ __align__(128) float g_ff[NTOK*DFF];

__device__ __forceinline__ uint32_t tf32u(float x) {
    uint32_t u;
    asm("cvt.rna.tf32.f32 %0, %1;" : "=r"(u) : "f"(x));
    return u;
}
__device__ __forceinline__ float tf32f(float x) { return __uint_as_float(tf32u(x)); }

// ---------------------------------------------------------------------------
// Embedding: h = tf32round(emb[x] + pe)
// ---------------------------------------------------------------------------
__global__ void embed_kernel(const int* __restrict__ x,
                             const float* __restrict__ emb,
                             const float* __restrict__ pe,
                             float* __restrict__ h)
{
    int tok = blockIdx.x;
    int s = tok & (SS-1);
    int id = x[tok];
    int t = threadIdx.x; // 0..127
    const float4* e4 = reinterpret_cast<const float4*>(emb + (size_t)id*DD);
    const float4* p4 = reinterpret_cast<const float4*>(pe + (size_t)s*DD);
    float4 ev = e4[t], pv = p4[t];
    float4 r;
    r.x = tf32f(ev.x+pv.x); r.y = tf32f(ev.y+pv.y);
    r.z = tf32f(ev.z+pv.z); r.w = tf32f(ev.w+pv.w);
    reinterpret_cast<float4*>(h + (size_t)tok*DD)[t] = r;
}

__device__ __forceinline__ float gelu_f(float x) {
    return 0.5f * x * (1.0f + tanhf(0.7978845608028654f * (x + 0.044715f*x*x*x)));
}

__device__ __forceinline__ void mma_tf32(float* c, const uint32_t* a, const uint32_t* b) {
    asm volatile(
        "mma.sync.aligned.m16n8k8.row.col.f32.tf32.tf32.f32 "
        "{%0,%1,%2,%3}, {%4,%5,%6,%7}, {%8,%9}, {%0,%1,%2,%3};"
        : "+f"(c[0]), "+f"(c[1]), "+f"(c[2]), "+f"(c[3])
        : "r"(a[0]), "r"(a[1]), "r"(a[2]), "r"(a[3]), "r"(b[0]), "r"(b[1]));
}

__device__ __forceinline__ void cp16(void* smem_dst, const void* gsrc) {
    uint32_t s = (uint32_t)__cvta_generic_to_shared(smem_dst);
    asm volatile("cp.async.cg.shared.global [%0], [%1], 16;" :: "r"(s), "l"(gsrc));
}
#define CP_COMMIT() asm volatile("cp.async.commit_group;")
#define CP_WAIT2()  asm volatile("cp.async.wait_group 2;")
#define CP_WAIT1()  asm volatile("cp.async.wait_group 1;")
#define CP_WAIT0()  asm volatile("cp.async.wait_group 0;")

// smem layout sizes (floats)
#define A_TILE_F (128*20)          // [128][20]
#define B_TILE_F(BN) (16*((BN)+8)) // [16][BN+8]

__device__ __forceinline__ uint32_t ldraw(const float& p) { return __float_as_uint(p); }

// ---------------------------------------------------------------------------
// Pipelined TF32 GEMM: C[M,N] = A[M,K] @ B[K,N] (+bias)(+res)(+gelu)(+round)
// A is pre-rounded to tf32 by its producer -> raw-bit fragment loads (no CVT).
// B (weights) converted at fragment load.
// CTA tile 128 x BN, BK=16, 4-stage cp.async, 1 sync/iter, 256 threads.
// ---------------------------------------------------------------------------
template<int BN, int WR>
__global__ __launch_bounds__(256, 2) void gemm_tf32p(
    const float* __restrict__ A, int lda,
    const float* __restrict__ B0, const float* __restrict__ B1, const float* __restrict__ B2,
    int ldb,
    const float* __restrict__ bias0, const float* __restrict__ bias1, const float* __restrict__ bias2,
    const float* __restrict__ res,
    float* __restrict__ C0, float* __restrict__ C1, float* __restrict__ C2,
    int ldc, int K, int act, int round_out)
{
    constexpr int MI = 128/(WR*16);
    constexpr int WC = 8/WR;
    constexpr int NI = BN/(WC*8);

    int z = blockIdx.z;
    const float* B    = (z == 0) ? B0    : ((z == 1) ? B1    : B2);
    const float* bias = (z == 0) ? bias0 : ((z == 1) ? bias1 : bias2);
    float*       C    = (z == 0) ? C0    : ((z == 1) ? C1    : C2);

    extern __shared__ float dsm[];
    float (*As)[128][20]  = reinterpret_cast<float(*)[128][20]>(dsm);
    float (*Bs)[16][BN+8] = reinterpret_cast<float(*)[16][BN+8]>(dsm + 4*A_TILE_F);

    int tid  = threadIdx.x;
    int lane = tid & 31, warp = tid >> 5;
    int g    = lane >> 2, tig = lane & 3;
    int mw   = warp % WR, nw = warp / WR;
    int wm   = mw * (MI*16);
    int wn   = nw * (NI*8);
    int m0   = blockIdx.y * 128, n0 = blockIdx.x * BN;

    int arow = tid >> 1, acol = (tid & 1) * 8;
    int brow = tid >> 4;
    int bcol = (BN == 64) ? (tid & 15) * 4 : (tid & 15) * 8;

    const float* Aptr = A + (size_t)(m0 + arow) * lda + acol;
    const float* Bptr = B + (size_t)brow * ldb + n0 + bcol;

    float acc[MI][NI][4];
#pragma unroll
    for (int mi = 0; mi < MI; mi++)
#pragma unroll
        for (int ni = 0; ni < NI; ni++)
#pragma unroll
            for (int r = 0; r < 4; r++) acc[mi][ni][r] = 0.f;

    int nk = K >> 4;

#pragma unroll
    for (int s = 0; s < 3; s++) {
        int k0 = s * 16;
        cp16(&As[s][arow][acol],     Aptr + k0);
        cp16(&As[s][arow][acol + 4], Aptr + k0 + 4);
        cp16(&Bs[s][brow][bcol],     Bptr + (size_t)k0 * ldb);
        if (BN == 128)
            cp16(&Bs[s][brow][bcol + 4], Bptr + (size_t)k0 * ldb + 4);
        CP_COMMIT();
    }

    for (int it = 0; it < nk; it++) {
        if (it + 2 < nk) CP_WAIT2();
        else if (it + 1 < nk) CP_WAIT1();
        else CP_WAIT0();
        __syncthreads();
        int s = it & 3;
#pragma unroll
        for (int kk = 0; kk < 16; kk += 8) {
            uint32_t af[MI][4], bf[NI][2];
#pragma unroll
            for (int mi = 0; mi < MI; mi++) {
                int r = wm + mi*16 + g;
                af[mi][0] = ldraw(As[s][r    ][kk+tig  ]);
                af[mi][1] = ldraw(As[s][r + 8][kk+tig  ]);
                af[mi][2] = ldraw(As[s][r    ][kk+tig+4]);
                af[mi][3] = ldraw(As[s][r + 8][kk+tig+4]);
            }
#pragma unroll
            for (int ni = 0; ni < NI; ni++) {
                int cc = wn + ni*8 + g;
                bf[ni][0] = tf32u(Bs[s][kk+tig  ][cc]);
                bf[ni][1] = tf32u(Bs[s][kk+tig+4][cc]);
            }
#pragma unroll
            for (int mi = 0; mi < MI; mi++)
#pragma unroll
                for (int ni = 0; ni < NI; ni++)
                    mma_tf32(acc[mi][ni], af[mi], bf[ni]);
        }
        int nx = it + 3;
        if (nx < nk) {
            int sn = nx & 3;
            int k0 = nx * 16;
            cp16(&As[sn][arow][acol],     Aptr + k0);
            cp16(&As[sn][arow][acol + 4], Aptr + k0 + 4);
            cp16(&Bs[sn][brow][bcol],     Bptr + (size_t)k0 * ldb);
            if (BN == 128)
                cp16(&Bs[sn][brow][bcol + 4], Bptr + (size_t)k0 * ldb + 4);
            CP_COMMIT();
        }
    }

#pragma unroll
    for (int mi = 0; mi < MI; mi++) {
        int row0 = m0 + wm + mi*16 + g;
#pragma unroll
        for (int ni = 0; ni < NI; ni++) {
            int col = n0 + wn + ni*8 + 2*tig;
            float b0 = 0.f, b1 = 0.f;
            if (bias) { b0 = bias[col]; b1 = bias[col+1]; }
            float v0 = acc[mi][ni][0] + b0;
            float v1 = acc[mi][ni][1] + b1;
            float v2 = acc[mi][ni][2] + b0;
            float v3 = acc[mi][ni][3] + b1;
            if (res) {
                const float* r0p = res + (size_t)row0 * ldc + col;
                const float* r1p = res + (size_t)(row0+8) * ldc + col;
                v0 += r0p[0]; v1 += r0p[1];
                v2 += r1p[0]; v3 += r1p[1];
            }
            if (act) {
                v0 = gelu_f(v0); v1 = gelu_f(v1);
                v2 = gelu_f(v2); v3 = gelu_f(v3);
            }
            if (round_out) {
                v0 = tf32f(v0); v1 = tf32f(v1);
                v2 = tf32f(v2); v3 = tf32f(v3);
            }
            *reinterpret_cast<float2*>(C + (size_t)row0 * ldc + col)     = make_float2(v0, v1);
            *reinterpret_cast<float2*>(C + (size_t)(row0+8) * ldc + col) = make_float2(v2, v3);
        }
    }
}

// ---------------------------------------------------------------------------
// Pipelined TF32 score GEMM: per (b,h) S = Q @ K^T * scale + mask
// Q,K pre-rounded -> zero CVTs. CTA 128x128, K=64, warps 2m x 4n.
// grid (4 ntile, 4 mtile, 32 bh)
// ---------------------------------------------------------------------------
__global__ __launch_bounds__(256, 2) void score_tf32p(
    const float* __restrict__ Q,
    const float* __restrict__ Kmat,
    const int* __restrict__ x,
    float* __restrict__ attn, int l, float scale)
{
    constexpr int MI = 4, NI = 4;

    extern __shared__ float dsm[];
    float (*As)[128][20] = reinterpret_cast<float(*)[128][20]>(dsm);
    float (*Bs)[128][20] = reinterpret_cast<float(*)[128][20]>(dsm + 4*A_TILE_F);

    int tid  = threadIdx.x;
    int lane = tid & 31, warp = tid >> 5;
    int g    = lane >> 2, tig = lane & 3;
    int mw   = warp & 1, nw = warp >> 1;
    int wm   = mw * 64;
    int wn   = nw * 32;
    int zz = blockIdx.z;
    int b = zz >> 3, hh = zz & 7;
    int m0 = blockIdx.y * 128, n0 = blockIdx.x * 128;

    const float* Abase = Q    + (size_t)b*SS*DD + hh*DKV;
    const float* Bbase = Kmat + (size_t)b*SS*DD + hh*DKV;
    float* out = attn + (((size_t)b*LL + l)*HH + hh) * (size_t)(SS*SS);

    int arow = tid >> 1, acol = (tid & 1) * 8;

    const float* Aptr = Abase + (size_t)(m0 + arow) * DD + acol;
    const float* Bptr = Bbase + (size_t)(n0 + arow) * DD + acol;

    float acc[MI][NI][4];
#pragma unroll
    for (int mi = 0; mi < MI; mi++)
#pragma unroll
        for (int ni = 0; ni < NI; ni++)
#pragma unroll
            for (int r = 0; r < 4; r++) acc[mi][ni][r] = 0.f;

    const int nk = DKV >> 4; // 4

#pragma unroll
    for (int s = 0; s < 3; s++) {
        int k0 = s * 16;
        cp16(&As[s][arow][acol],     Aptr + k0);
        cp16(&As[s][arow][acol + 4], Aptr + k0 + 4);
        cp16(&Bs[s][arow][acol],     Bptr + k0);
        cp16(&Bs[s][arow][acol + 4], Bptr + k0 + 4);
        CP_COMMIT();
    }

#pragma unroll
    for (int it = 0; it < nk; it++) {
        if (it + 2 < nk) CP_WAIT2();
        else if (it + 1 < nk) CP_WAIT1();
        else CP_WAIT0();
        __syncthreads();
        int s = it & 3;
#pragma unroll
        for (int kk = 0; kk < 16; kk += 8) {
            uint32_t af[MI][4], bf[NI][2];
#pragma unroll
            for (int mi = 0; mi < MI; mi++) {
                int r = wm + mi*16 + g;
                af[mi][0] = ldraw(As[s][r    ][kk+tig  ]);
                af[mi][1] = ldraw(As[s][r + 8][kk+tig  ]);
                af[mi][2] = ldraw(As[s][r    ][kk+tig+4]);
                af[mi][3] = ldraw(As[s][r + 8][kk+tig+4]);
            }
#pragma unroll
            for (int ni = 0; ni < NI; ni++) {
                int cc = wn + ni*8 + g;
                bf[ni][0] = ldraw(Bs[s][cc][kk+tig  ]);
                bf[ni][1] = ldraw(Bs[s][cc][kk+tig+4]);
            }
#pragma unroll
            for (int mi = 0; mi < MI; mi++)
#pragma unroll
                for (int ni = 0; ni < NI; ni++)
                    mma_tf32(acc[mi][ni], af[mi], bf[ni]);
        }
        int nx = it + 3;
        if (nx < nk) {
            int sn = nx & 3;
            int k0 = nx * 16;
            cp16(&As[sn][arow][acol],     Aptr + k0);
            cp16(&As[sn][arow][acol + 4], Aptr + k0 + 4);
            cp16(&Bs[sn][arow][acol],     Bptr + k0);
            cp16(&Bs[sn][arow][acol + 4], Bptr + k0 + 4);
            CP_COMMIT();
        }
    }

    const int* xb = x + b*SS;
#pragma unroll
    for (int mi = 0; mi < MI; mi++) {
        int row0 = m0 + wm + mi*16 + g;
#pragma unroll
        for (int ni = 0; ni < NI; ni++) {
            int col = n0 + wn + ni*8 + 2*tig;
            bool msk0 = (xb[col]   == 0);
            bool msk1 = (xb[col+1] == 0);
            float v0 = msk0 ? -1e9f : acc[mi][ni][0] * scale;
            float v1 = msk1 ? -1e9f : acc[mi][ni][1] * scale;
            float v2 = msk0 ? -1e9f : acc[mi][ni][2] * scale;
            float v3 = msk1 ? -1e9f : acc[mi][ni][3] * scale;
            *reinterpret_cast<float2*>(out + (size_t)row0 * SS + col)     = make_float2(v0, v1);
            *reinterpret_cast<float2*>(out + (size_t)(row0+8) * SS + col) = make_float2(v2, v3);
        }
    }
}

// ---------------------------------------------------------------------------
// Pipelined TF32 ctx GEMM: per (b,h) C[512,64] = P[512,512] @ V[512,64]
// P (attn) converted at load; V pre-rounded -> raw. Output rounded (feeds WO).
// CTA 128x64, warps 4m x 2n. grid (4 mtile, 32 bh)
// ---------------------------------------------------------------------------
__global__ __launch_bounds__(256, 2) void ctx_tf32p(
    const float* __restrict__ attn,
    const float* __restrict__ V,
    float* __restrict__ C, int l)
{
    constexpr int MI = 2, NI = 4;

    extern __shared__ float dsm[];
    float (*As)[128][20] = reinterpret_cast<float(*)[128][20]>(dsm);
    float (*Bs)[16][72]  = reinterpret_cast<float(*)[16][72]>(dsm + 4*A_TILE_F);

    int tid  = threadIdx.x;
    int lane = tid & 31, warp = tid >> 5;
    int g    = lane >> 2, tig = lane & 3;
    int wm   = (warp & 3) * 32;
    int wn   = (warp >> 2) * 32;
    int zz = blockIdx.y;
    int b = zz >> 3, hh = zz & 7;
    int m0 = blockIdx.x * 128;

    const float* Abase = attn + (((size_t)b*LL + l)*HH + hh) * (size_t)(SS*SS);
    const float* Bbase = V + (size_t)b*SS*DD + hh*DKV;
    float* Cb = C + (size_t)b*SS*DD + hh*DKV;

    int arow = tid >> 1, acol = (tid & 1) * 8;
    int brow = tid >> 4, bcol = (tid & 15) * 4;

    const float* Aptr = Abase + (size_t)(m0 + arow) * SS + acol;
    const float* Bptr = Bbase + (size_t)brow * DD + bcol;

    float acc[MI][NI][4];
#pragma unroll
    for (int mi = 0; mi < MI; mi++)
#pragma unroll
        for (int ni = 0; ni < NI; ni++)
#pragma unroll
            for (int r = 0; r < 4; r++) acc[mi][ni][r] = 0.f;

    const int nk = SS >> 4; // 32

#pragma unroll
    for (int s = 0; s < 3; s++) {
        int k0 = s * 16;
        cp16(&As[s][arow][acol],     Aptr + k0);
        cp16(&As[s][arow][acol + 4], Aptr + k0 + 4);
        cp16(&Bs[s][brow][bcol],     Bptr + (size_t)k0 * DD);
        CP_COMMIT();
    }

    for (int it = 0; it < nk; it++) {
        if (it + 2 < nk) CP_WAIT2();
        else if (it + 1 < nk) CP_WAIT1();
        else CP_WAIT0();
        __syncthreads();
        int s = it & 3;
#pragma unroll
        for (int kk = 0; kk < 16; kk += 8) {
            uint32_t af[MI][4], bf[NI][2];
#pragma unroll
            for (int mi = 0; mi < MI; mi++) {
                int r = wm + mi*16 + g;
                af[mi][0] = tf32u(As[s][r    ][kk+tig  ]);
                af[mi][1] = tf32u(As[s][r + 8][kk+tig  ]);
                af[mi][2] = tf32u(As[s][r    ][kk+tig+4]);
                af[mi][3] = tf32u(As[s][r + 8][kk+tig+4]);
            }
#pragma unroll
            for (int ni = 0; ni < NI; ni++) {
                int cc = wn + ni*8 + g;
                bf[ni][0] = ldraw(Bs[s][kk+tig  ][cc]);
                bf[ni][1] = ldraw(Bs[s][kk+tig+4][cc]);
            }
#pragma unroll
            for (int mi = 0; mi < MI; mi++)
#pragma unroll
                for (int ni = 0; ni < NI; ni++)
                    mma_tf32(acc[mi][ni], af[mi], bf[ni]);
        }
        int nx = it + 3;
        if (nx < nk) {
            int sn = nx & 3;
            int k0 = nx * 16;
            cp16(&As[sn][arow][acol],     Aptr + k0);
            cp16(&As[sn][arow][acol + 4], Aptr + k0 + 4);
            cp16(&Bs[sn][brow][bcol],     Bptr + (size_t)k0 * DD);
            CP_COMMIT();
        }
    }

#pragma unroll
    for (int mi = 0; mi < MI; mi++) {
        int row0 = m0 + wm + mi*16 + g;
#pragma unroll
        for (int ni = 0; ni < NI; ni++) {
            int col = wn + ni*8 + 2*tig;
            *reinterpret_cast<float2*>(Cb + (size_t)row0 * DD + col)
                = make_float2(tf32f(acc[mi][ni][0]), tf32f(acc[mi][ni][1]));
            *reinterpret_cast<float2*>(Cb + (size_t)(row0+8) * DD + col)
                = make_float2(tf32f(acc[mi][ni][2]), tf32f(acc[mi][ni][3]));
        }
    }
}

// ---------------------------------------------------------------------------
__global__ __launch_bounds__(128) void softmax_kernel(float* __restrict__ attn, int l)
{
    __shared__ float red[8];
    int row = blockIdx.x;
    int b = row >> 12;
    int rem = row & 4095;
    float* p = attn + (size_t)b*(LL*HH*SS*SS) + (size_t)l*(HH*SS*SS) + (size_t)rem*SS;
    int t = threadIdx.x;
    int lane = t & 31, wid = t >> 5;

    float v[4];
#pragma unroll
    for (int i = 0; i < 4; i++) v[i] = p[t + 128*i];

    float mx = fmaxf(fmaxf(v[0],v[1]), fmaxf(v[2],v[3]));
#pragma unroll
    for (int o = 16; o > 0; o >>= 1) mx = fmaxf(mx, __shfl_xor_sync(0xffffffffu, mx, o));
    if (lane == 0) red[wid] = mx;
    __syncthreads();
    mx = fmaxf(fmaxf(red[0],red[1]), fmaxf(red[2],red[3]));

    float s = 0.f;
#pragma unroll
    for (int i = 0; i < 4; i++) { v[i] = __expf(v[i] - mx); s += v[i]; }
#pragma unroll
    for (int o = 16; o > 0; o >>= 1) s += __shfl_xor_sync(0xffffffffu, s, o);
    if (lane == 0) red[4 + wid] = s;
    __syncthreads();
    s = red[4] + red[5] + red[6] + red[7];
    float inv = 1.0f / s;
#pragma unroll
    for (int i = 0; i < 4; i++) p[t + 128*i] = v[i] * inv;
}

// ---------------------------------------------------------------------------
__global__ __launch_bounds__(128) void ln_kernel(
    const float* __restrict__ in,
    const float* __restrict__ g,
    const float* __restrict__ bta,
    float* __restrict__ out, int round_out)
{
    __shared__ float red[8];
    int row = blockIdx.x;
    const float* p = in + (size_t)row*DD;
    float* o = out + (size_t)row*DD;
    int t = threadIdx.x;
    int lane = t & 31, wid = t >> 5;

    float v[4];
    float s = 0.f, sq = 0.f;
#pragma unroll
    for (int i = 0; i < 4; i++) { v[i] = p[t + 128*i]; s += v[i]; sq += v[i]*v[i]; }
#pragma unroll
    for (int o2 = 16; o2 > 0; o2 >>= 1) {
        s  += __shfl_xor_sync(0xffffffffu, s,  o2);
        sq += __shfl_xor_sync(0xffffffffu, sq, o2);
    }
    if (lane == 0) { red[wid] = s; red[4+wid] = sq; }
    __syncthreads();
    s  = red[0]+red[1]+red[2]+red[3];
    sq = red[4]+red[5]+red[6]+red[7];
    float mu = s * (1.0f/DD);
    float var = sq * (1.0f/DD) - mu*mu;
    float rstd = rsqrtf(var + EPS);
#pragma unroll
    for (int i = 0; i < 4; i++) {
        int col = t + 128*i;
        float r = (v[i] - mu) * rstd * g[col] + bta[col];
        o[col] = round_out ? tf32f(r) : r;
    }
}

// ---------------------------------------------------------------------------
extern "C" void kernel_launch(void* const* d_in, const int* in_sizes, int n_in,
                              void* d_out, int out_size)
{
    const int*   x    = (const int*)  d_in[0];
    const float* emb  = (const float*)d_in[1];
    const float* pe   = (const float*)d_in[2];
    const float* WQ   = (const float*)d_in[3];
    const float* bQ   = (const float*)d_in[4];
    const float* WK   = (const float*)d_in[5];
    const float* bK   = (const float*)d_in[6];
    const float* WV   = (const float*)d_in[7];
    const float* bV   = (const float*)d_in[8];
    const float* WO   = (const float*)d_in[9];
    const float* bO   = (const float*)d_in[10];
    const float* ln1g = (const float*)d_in[11];
    const float* ln1b = (const float*)d_in[12];
    const float* W1   = (const float*)d_in[13];
    const float* b1   = (const float*)d_in[14];
    const float* W2   = (const float*)d_in[15];
    const float* b2   = (const float*)d_in[16];
    const float* ln2g = (const float*)d_in[17];
    const float* ln2b = (const float*)d_in[18];

    float* out  = (float*)d_out;
    float* attn = out + (size_t)NTOK*DD;

    float *h, *q, *k, *v, *ctx, *tmp, *ff;
    cudaGetSymbolAddress((void**)&h,   g_h);
    cudaGetSymbolAddress((void**)&q,   g_q);
    cudaGetSymbolAddress((void**)&k,   g_k);
    cudaGetSymbolAddress((void**)&v,   g_v);
    cudaGetSymbolAddress((void**)&ctx, g_ctx);
    cudaGetSymbolAddress((void**)&tmp, g_tmp);
    cudaGetSymbolAddress((void**)&ff,  g_ff);

    // dynamic smem sizes (bytes)
    const int SM_D128 = (4*A_TILE_F + 4*B_TILE_F(128)) * 4;  // 75776
    const int SM_D64  = (4*A_TILE_F + 4*B_TILE_F(64))  * 4;  // 59392
    const int SM_SC   = (4*A_TILE_F + 4*A_TILE_F)      * 4;  // 81920

    static int attr_done = 0;
    if (!attr_done) {
        cudaFuncSetAttribute(gemm_tf32p<128,2>, cudaFuncAttributeMaxDynamicSharedMemorySize, SM_D128);
        cudaFuncSetAttribute(gemm_tf32p<64,4>,  cudaFuncAttributeMaxDynamicSharedMemorySize, SM_D64);
        cudaFuncSetAttribute(score_tf32p,       cudaFuncAttributeMaxDynamicSharedMemorySize, SM_SC);
        cudaFuncSetAttribute(ctx_tf32p,         cudaFuncAttributeMaxDynamicSharedMemorySize, SM_D64);
        attr_done = 1;
    }

    const float scale = 0.125f;

    embed_kernel<<<NTOK, 128>>>(x, emb, pe, h);

    for (int l = 0; l < LL; l++) {
        const float* wq = WQ + (size_t)l*DD*DD;
        const float* wk = WK + (size_t)l*DD*DD;
        const float* wv = WV + (size_t)l*DD*DD;
        const float* wo = WO + (size_t)l*DD*DD;
        const float* w1 = W1 + (size_t)l*DD*DFF;
        const float* w2 = W2 + (size_t)l*DFF*DD;

        // fused QKV (outputs rounded: feed score/ctx raw)
        gemm_tf32p<128,2><<<dim3(4,16,3), 256, SM_D128>>>(h, DD,
            wq, wk, wv, DD,
            bQ + l*DD, bK + l*DD, bV + l*DD,
            nullptr,
            q, k, v, DD, DD, 0, 1);

        score_tf32p<<<dim3(4,4,32), 256, SM_SC>>>(q, k, x, attn, l, scale);
        softmax_kernel<<<BB*HH*SS, 128>>>(attn, l);
        ctx_tf32p<<<dim3(4,32), 256, SM_D64>>>(attn, v, ctx, l);

        // WO (output tmp feeds LN only: no rounding)
        gemm_tf32p<64,4><<<dim3(8,16,1), 256, SM_D64>>>(ctx, DD,
            wo, wo, wo, DD,
            bO + l*DD, bO + l*DD, bO + l*DD,
            h,
            tmp, tmp, tmp, DD, DD, 0, 0);
        ln_kernel<<<NTOK, 128>>>(tmp, ln1g + l*DD, ln1b + l*DD, h, 1);

        // FFN1 (output ff rounded: feeds FFN2 A)
        gemm_tf32p<128,2><<<dim3(16,16,1), 256, SM_D128>>>(h, DD,
            w1, w1, w1, DFF,
            b1 + l*DFF, b1 + l*DFF, b1 + l*DFF,
            nullptr,
            ff, ff, ff, DFF, DD, 1, 1);

        // FFN2 (output tmp feeds LN only: no rounding)
        gemm_tf32p<64,4><<<dim3(8,16,1), 256, SM_D64>>>(ff, DFF,
            w2, w2, w2, DD,
            b2 + l*DD, b2 + l*DD, b2 + l*DD,
            h,
            tmp, tmp, tmp, DD, DFF, 0, 0);

        float* lnout = (l == LL-1) ? out : h;
        int roundln = (l == LL-1) ? 0 : 1;
        ln_kernel<<<NTOK, 128>>>(tmp, ln2g + l*DD, ln2b + l*DD, lnout, roundln);
    }
}

// round 10
// speedup vs baseline: 5.0503x; 1.0020x over previous
#include <cuda_runtime.h>
#include <cuda_bf16.h>
#include <math.h>
#include <stdint.h>

// Problem constants
#define BB 4
#define SS 512
#define DD 512
#define HH 8
#define DKV 64
#define DFF 2048
#define LL 6
#define NTOK (BB*SS)          // 2048
#define EPS 1e-5f

// Scratch (device globals; no allocation allowed)
__device__ __align__(128) float g_h[NTOK*DD];     // fp32 residual stream
__device__ __align__(128) float g_hr[NTOK*DD];    // tf32-rounded copy (GEMM A input)
__device__ __align__(128) float g_q[NTOK*DD];
__device__ __align__(128) float g_k[NTOK*DD];
__device__ __align__(128) float g_v[NTOK*DD];
__device__ __align__(128) float g_ctx[NTOK*DD];
__device__ __align__(128) float g_tmp[NTOK*DD];
__device__ __align__(128) float g_ff[NTOK*DFF];

__device__ __forceinline__ uint32_t tf32u(float x) {
    uint32_t u;
    asm("cvt.rna.tf32.f32 %0, %1;" : "=r"(u) : "f"(x));
    return u;
}
__device__ __forceinline__ float tf32f(float x) { return __uint_as_float(tf32u(x)); }

// ---------------------------------------------------------------------------
// Embedding: h = emb[x] + pe (fp32) ; hr = tf32round(h)
// ---------------------------------------------------------------------------
__global__ void embed_kernel(const int* __restrict__ x,
                             const float* __restrict__ emb,
                             const float* __restrict__ pe,
                             float* __restrict__ h,
                             float* __restrict__ hr)
{
    int tok = blockIdx.x;
    int s = tok & (SS-1);
    int id = x[tok];
    int t = threadIdx.x; // 0..127
    const float4* e4 = reinterpret_cast<const float4*>(emb + (size_t)id*DD);
    const float4* p4 = reinterpret_cast<const float4*>(pe + (size_t)s*DD);
    float4 ev = e4[t], pv = p4[t];
    float4 r; r.x=ev.x+pv.x; r.y=ev.y+pv.y; r.z=ev.z+pv.z; r.w=ev.w+pv.w;
    reinterpret_cast<float4*>(h + (size_t)tok*DD)[t] = r;
    float4 rr; rr.x=tf32f(r.x); rr.y=tf32f(r.y); rr.z=tf32f(r.z); rr.w=tf32f(r.w);
    reinterpret_cast<float4*>(hr + (size_t)tok*DD)[t] = rr;
}

__device__ __forceinline__ float gelu_f(float x) {
    return 0.5f * x * (1.0f + tanhf(0.7978845608028654f * (x + 0.044715f*x*x*x)));
}

__device__ __forceinline__ void mma_tf32(float* c, const uint32_t* a, const uint32_t* b) {
    asm volatile(
        "mma.sync.aligned.m16n8k8.row.col.f32.tf32.tf32.f32 "
        "{%0,%1,%2,%3}, {%4,%5,%6,%7}, {%8,%9}, {%0,%1,%2,%3};"
        : "+f"(c[0]), "+f"(c[1]), "+f"(c[2]), "+f"(c[3])
        : "r"(a[0]), "r"(a[1]), "r"(a[2]), "r"(a[3]), "r"(b[0]), "r"(b[1]));
}

__device__ __forceinline__ void cp16(void* smem_dst, const void* gsrc) {
    uint32_t s = (uint32_t)__cvta_generic_to_shared(smem_dst);
    asm volatile("cp.async.cg.shared.global [%0], [%1], 16;" :: "r"(s), "l"(gsrc));
}
#define CP_COMMIT() asm volatile("cp.async.commit_group;")
#define CP_WAIT2()  asm volatile("cp.async.wait_group 2;")
#define CP_WAIT1()  asm volatile("cp.async.wait_group 1;")
#define CP_WAIT0()  asm volatile("cp.async.wait_group 0;")

// smem layout sizes (floats)
#define A_TILE_F (128*20)          // [128][20]
#define B_TILE_F(BN) (16*((BN)+8)) // [16][BN+8]

__device__ __forceinline__ uint32_t ldraw(const float& p) { return __float_as_uint(p); }

// ---------------------------------------------------------------------------
// Pipelined TF32 GEMM: C[M,N] = A[M,K] @ B[K,N] (+bias)(+res)(+gelu)(+round)
// A is pre-rounded to tf32 by its producer -> raw-bit fragment loads (no CVT).
// B (weights) converted at fragment load.
// CTA tile 128 x BN, BK=16, 4-stage cp.async, 1 sync/iter, 256 threads.
// ---------------------------------------------------------------------------
template<int BN, int WR>
__global__ __launch_bounds__(256, 2) void gemm_tf32p(
    const float* __restrict__ A, int lda,
    const float* __restrict__ B0, const float* __restrict__ B1, const float* __restrict__ B2,
    int ldb,
    const float* __restrict__ bias0, const float* __restrict__ bias1, const float* __restrict__ bias2,
    const float* __restrict__ res,
    float* __restrict__ C0, float* __restrict__ C1, float* __restrict__ C2,
    int ldc, int K, int act, int round_out)
{
    constexpr int MI = 128/(WR*16);
    constexpr int WC = 8/WR;
    constexpr int NI = BN/(WC*8);

    int z = blockIdx.z;
    const float* B    = (z == 0) ? B0    : ((z == 1) ? B1    : B2);
    const float* bias = (z == 0) ? bias0 : ((z == 1) ? bias1 : bias2);
    float*       C    = (z == 0) ? C0    : ((z == 1) ? C1    : C2);

    extern __shared__ float dsm[];
    float (*As)[128][20]  = reinterpret_cast<float(*)[128][20]>(dsm);
    float (*Bs)[16][BN+8] = reinterpret_cast<float(*)[16][BN+8]>(dsm + 4*A_TILE_F);

    int tid  = threadIdx.x;
    int lane = tid & 31, warp = tid >> 5;
    int g    = lane >> 2, tig = lane & 3;
    int mw   = warp % WR, nw = warp / WR;
    int wm   = mw * (MI*16);
    int wn   = nw * (NI*8);
    int m0   = blockIdx.y * 128, n0 = blockIdx.x * BN;

    int arow = tid >> 1, acol = (tid & 1) * 8;
    int brow = tid >> 4;
    int bcol = (BN == 64) ? (tid & 15) * 4 : (tid & 15) * 8;

    const float* Aptr = A + (size_t)(m0 + arow) * lda + acol;
    const float* Bptr = B + (size_t)brow * ldb + n0 + bcol;

    float acc[MI][NI][4];
#pragma unroll
    for (int mi = 0; mi < MI; mi++)
#pragma unroll
        for (int ni = 0; ni < NI; ni++)
#pragma unroll
            for (int r = 0; r < 4; r++) acc[mi][ni][r] = 0.f;

    int nk = K >> 4;

#pragma unroll
    for (int s = 0; s < 3; s++) {
        int k0 = s * 16;
        cp16(&As[s][arow][acol],     Aptr + k0);
        cp16(&As[s][arow][acol + 4], Aptr + k0 + 4);
        cp16(&Bs[s][brow][bcol],     Bptr + (size_t)k0 * ldb);
        if (BN == 128)
            cp16(&Bs[s][brow][bcol + 4], Bptr + (size_t)k0 * ldb + 4);
        CP_COMMIT();
    }

    for (int it = 0; it < nk; it++) {
        if (it + 2 < nk) CP_WAIT2();
        else if (it + 1 < nk) CP_WAIT1();
        else CP_WAIT0();
        __syncthreads();
        int s = it & 3;
#pragma unroll
        for (int kk = 0; kk < 16; kk += 8) {
            uint32_t af[MI][4], bf[NI][2];
#pragma unroll
            for (int mi = 0; mi < MI; mi++) {
                int r = wm + mi*16 + g;
                af[mi][0] = ldraw(As[s][r    ][kk+tig  ]);
                af[mi][1] = ldraw(As[s][r + 8][kk+tig  ]);
                af[mi][2] = ldraw(As[s][r    ][kk+tig+4]);
                af[mi][3] = ldraw(As[s][r + 8][kk+tig+4]);
            }
#pragma unroll
            for (int ni = 0; ni < NI; ni++) {
                int cc = wn + ni*8 + g;
                bf[ni][0] = tf32u(Bs[s][kk+tig  ][cc]);
                bf[ni][1] = tf32u(Bs[s][kk+tig+4][cc]);
            }
#pragma unroll
            for (int mi = 0; mi < MI; mi++)
#pragma unroll
                for (int ni = 0; ni < NI; ni++)
                    mma_tf32(acc[mi][ni], af[mi], bf[ni]);
        }
        int nx = it + 3;
        if (nx < nk) {
            int sn = nx & 3;
            int k0 = nx * 16;
            cp16(&As[sn][arow][acol],     Aptr + k0);
            cp16(&As[sn][arow][acol + 4], Aptr + k0 + 4);
            cp16(&Bs[sn][brow][bcol],     Bptr + (size_t)k0 * ldb);
            if (BN == 128)
                cp16(&Bs[sn][brow][bcol + 4], Bptr + (size_t)k0 * ldb + 4);
            CP_COMMIT();
        }
    }

#pragma unroll
    for (int mi = 0; mi < MI; mi++) {
        int row0 = m0 + wm + mi*16 + g;
#pragma unroll
        for (int ni = 0; ni < NI; ni++) {
            int col = n0 + wn + ni*8 + 2*tig;
            float b0 = 0.f, b1 = 0.f;
            if (bias) { b0 = bias[col]; b1 = bias[col+1]; }
            float v0 = acc[mi][ni][0] + b0;
            float v1 = acc[mi][ni][1] + b1;
            float v2 = acc[mi][ni][2] + b0;
            float v3 = acc[mi][ni][3] + b1;
            if (res) {
                const float* r0p = res + (size_t)row0 * ldc + col;
                const float* r1p = res + (size_t)(row0+8) * ldc + col;
                v0 += r0p[0]; v1 += r0p[1];
                v2 += r1p[0]; v3 += r1p[1];
            }
            if (act) {
                v0 = gelu_f(v0); v1 = gelu_f(v1);
                v2 = gelu_f(v2); v3 = gelu_f(v3);
            }
            if (round_out) {
                v0 = tf32f(v0); v1 = tf32f(v1);
                v2 = tf32f(v2); v3 = tf32f(v3);
            }
            *reinterpret_cast<float2*>(C + (size_t)row0 * ldc + col)     = make_float2(v0, v1);
            *reinterpret_cast<float2*>(C + (size_t)(row0+8) * ldc + col) = make_float2(v2, v3);
        }
    }
}

// ---------------------------------------------------------------------------
// Pipelined TF32 score GEMM: per (b,h) S = Q @ K^T * scale + mask
// Q,K pre-rounded -> zero CVTs. CTA 128x128, K=64, warps 2m x 4n.
// grid (4 ntile, 4 mtile, 32 bh)
// ---------------------------------------------------------------------------
__global__ __launch_bounds__(256, 2) void score_tf32p(
    const float* __restrict__ Q,
    const float* __restrict__ Kmat,
    const int* __restrict__ x,
    float* __restrict__ attn, int l, float scale)
{
    constexpr int MI = 4, NI = 4;

    extern __shared__ float dsm[];
    float (*As)[128][20] = reinterpret_cast<float(*)[128][20]>(dsm);
    float (*Bs)[128][20] = reinterpret_cast<float(*)[128][20]>(dsm + 4*A_TILE_F);

    int tid  = threadIdx.x;
    int lane = tid & 31, warp = tid >> 5;
    int g    = lane >> 2, tig = lane & 3;
    int mw   = warp & 1, nw = warp >> 1;
    int wm   = mw * 64;
    int wn   = nw * 32;
    int zz = blockIdx.z;
    int b = zz >> 3, hh = zz & 7;
    int m0 = blockIdx.y * 128, n0 = blockIdx.x * 128;

    const float* Abase = Q    + (size_t)b*SS*DD + hh*DKV;
    const float* Bbase = Kmat + (size_t)b*SS*DD + hh*DKV;
    float* out = attn + (((size_t)b*LL + l)*HH + hh) * (size_t)(SS*SS);

    int arow = tid >> 1, acol = (tid & 1) * 8;

    const float* Aptr = Abase + (size_t)(m0 + arow) * DD + acol;
    const float* Bptr = Bbase + (size_t)(n0 + arow) * DD + acol;

    float acc[MI][NI][4];
#pragma unroll
    for (int mi = 0; mi < MI; mi++)
#pragma unroll
        for (int ni = 0; ni < NI; ni++)
#pragma unroll
            for (int r = 0; r < 4; r++) acc[mi][ni][r] = 0.f;

    const int nk = DKV >> 4; // 4

#pragma unroll
    for (int s = 0; s < 3; s++) {
        int k0 = s * 16;
        cp16(&As[s][arow][acol],     Aptr + k0);
        cp16(&As[s][arow][acol + 4], Aptr + k0 + 4);
        cp16(&Bs[s][arow][acol],     Bptr + k0);
        cp16(&Bs[s][arow][acol + 4], Bptr + k0 + 4);
        CP_COMMIT();
    }

#pragma unroll
    for (int it = 0; it < nk; it++) {
        if (it + 2 < nk) CP_WAIT2();
        else if (it + 1 < nk) CP_WAIT1();
        else CP_WAIT0();
        __syncthreads();
        int s = it & 3;
#pragma unroll
        for (int kk = 0; kk < 16; kk += 8) {
            uint32_t af[MI][4], bf[NI][2];
#pragma unroll
            for (int mi = 0; mi < MI; mi++) {
                int r = wm + mi*16 + g;
                af[mi][0] = ldraw(As[s][r    ][kk+tig  ]);
                af[mi][1] = ldraw(As[s][r + 8][kk+tig  ]);
                af[mi][2] = ldraw(As[s][r    ][kk+tig+4]);
                af[mi][3] = ldraw(As[s][r + 8][kk+tig+4]);
            }
#pragma unroll
            for (int ni = 0; ni < NI; ni++) {
                int cc = wn + ni*8 + g;
                bf[ni][0] = ldraw(Bs[s][cc][kk+tig  ]);
                bf[ni][1] = ldraw(Bs[s][cc][kk+tig+4]);
            }
#pragma unroll
            for (int mi = 0; mi < MI; mi++)
#pragma unroll
                for (int ni = 0; ni < NI; ni++)
                    mma_tf32(acc[mi][ni], af[mi], bf[ni]);
        }
        int nx = it + 3;
        if (nx < nk) {
            int sn = nx & 3;
            int k0 = nx * 16;
            cp16(&As[sn][arow][acol],     Aptr + k0);
            cp16(&As[sn][arow][acol + 4], Aptr + k0 + 4);
            cp16(&Bs[sn][arow][acol],     Bptr + k0);
            cp16(&Bs[sn][arow][acol + 4], Bptr + k0 + 4);
            CP_COMMIT();
        }
    }

    const int* xb = x + b*SS;
#pragma unroll
    for (int mi = 0; mi < MI; mi++) {
        int row0 = m0 + wm + mi*16 + g;
#pragma unroll
        for (int ni = 0; ni < NI; ni++) {
            int col = n0 + wn + ni*8 + 2*tig;
            bool msk0 = (xb[col]   == 0);
            bool msk1 = (xb[col+1] == 0);
            float v0 = msk0 ? -1e9f : acc[mi][ni][0] * scale;
            float v1 = msk1 ? -1e9f : acc[mi][ni][1] * scale;
            float v2 = msk0 ? -1e9f : acc[mi][ni][2] * scale;
            float v3 = msk1 ? -1e9f : acc[mi][ni][3] * scale;
            *reinterpret_cast<float2*>(out + (size_t)row0 * SS + col)     = make_float2(v0, v1);
            *reinterpret_cast<float2*>(out + (size_t)(row0+8) * SS + col) = make_float2(v2, v3);
        }
    }
}

// ---------------------------------------------------------------------------
// Pipelined TF32 ctx GEMM: per (b,h) C[512,64] = P[512,512] @ V[512,64]
// P (attn) converted at load; V pre-rounded -> raw. Output rounded (feeds WO).
// CTA 128x64, warps 4m x 2n. grid (4 mtile, 32 bh)
// ---------------------------------------------------------------------------
__global__ __launch_bounds__(256, 2) void ctx_tf32p(
    const float* __restrict__ attn,
    const float* __restrict__ V,
    float* __restrict__ C, int l)
{
    constexpr int MI = 2, NI = 4;

    extern __shared__ float dsm[];
    float (*As)[128][20] = reinterpret_cast<float(*)[128][20]>(dsm);
    float (*Bs)[16][72]  = reinterpret_cast<float(*)[16][72]>(dsm + 4*A_TILE_F);

    int tid  = threadIdx.x;
    int lane = tid & 31, warp = tid >> 5;
    int g    = lane >> 2, tig = lane & 3;
    int wm   = (warp & 3) * 32;
    int wn   = (warp >> 2) * 32;
    int zz = blockIdx.y;
    int b = zz >> 3, hh = zz & 7;
    int m0 = blockIdx.x * 128;

    const float* Abase = attn + (((size_t)b*LL + l)*HH + hh) * (size_t)(SS*SS);
    const float* Bbase = V + (size_t)b*SS*DD + hh*DKV;
    float* Cb = C + (size_t)b*SS*DD + hh*DKV;

    int arow = tid >> 1, acol = (tid & 1) * 8;
    int brow = tid >> 4, bcol = (tid & 15) * 4;

    const float* Aptr = Abase + (size_t)(m0 + arow) * SS + acol;
    const float* Bptr = Bbase + (size_t)brow * DD + bcol;

    float acc[MI][NI][4];
#pragma unroll
    for (int mi = 0; mi < MI; mi++)
#pragma unroll
        for (int ni = 0; ni < NI; ni++)
#pragma unroll
            for (int r = 0; r < 4; r++) acc[mi][ni][r] = 0.f;

    const int nk = SS >> 4; // 32

#pragma unroll
    for (int s = 0; s < 3; s++) {
        int k0 = s * 16;
        cp16(&As[s][arow][acol],     Aptr + k0);
        cp16(&As[s][arow][acol + 4], Aptr + k0 + 4);
        cp16(&Bs[s][brow][bcol],     Bptr + (size_t)k0 * DD);
        CP_COMMIT();
    }

    for (int it = 0; it < nk; it++) {
        if (it + 2 < nk) CP_WAIT2();
        else if (it + 1 < nk) CP_WAIT1();
        else CP_WAIT0();
        __syncthreads();
        int s = it & 3;
#pragma unroll
        for (int kk = 0; kk < 16; kk += 8) {
            uint32_t af[MI][4], bf[NI][2];
#pragma unroll
            for (int mi = 0; mi < MI; mi++) {
                int r = wm + mi*16 + g;
                af[mi][0] = tf32u(As[s][r    ][kk+tig  ]);
                af[mi][1] = tf32u(As[s][r + 8][kk+tig  ]);
                af[mi][2] = tf32u(As[s][r    ][kk+tig+4]);
                af[mi][3] = tf32u(As[s][r + 8][kk+tig+4]);
            }
#pragma unroll
            for (int ni = 0; ni < NI; ni++) {
                int cc = wn + ni*8 + g;
                bf[ni][0] = ldraw(Bs[s][kk+tig  ][cc]);
                bf[ni][1] = ldraw(Bs[s][kk+tig+4][cc]);
            }
#pragma unroll
            for (int mi = 0; mi < MI; mi++)
#pragma unroll
                for (int ni = 0; ni < NI; ni++)
                    mma_tf32(acc[mi][ni], af[mi], bf[ni]);
        }
        int nx = it + 3;
        if (nx < nk) {
            int sn = nx & 3;
            int k0 = nx * 16;
            cp16(&As[sn][arow][acol],     Aptr + k0);
            cp16(&As[sn][arow][acol + 4], Aptr + k0 + 4);
            cp16(&Bs[sn][brow][bcol],     Bptr + (size_t)k0 * DD);
            CP_COMMIT();
        }
    }

#pragma unroll
    for (int mi = 0; mi < MI; mi++) {
        int row0 = m0 + wm + mi*16 + g;
#pragma unroll
        for (int ni = 0; ni < NI; ni++) {
            int col = wn + ni*8 + 2*tig;
            *reinterpret_cast<float2*>(Cb + (size_t)row0 * DD + col)
                = make_float2(tf32f(acc[mi][ni][0]), tf32f(acc[mi][ni][1]));
            *reinterpret_cast<float2*>(Cb + (size_t)(row0+8) * DD + col)
                = make_float2(tf32f(acc[mi][ni][2]), tf32f(acc[mi][ni][3]));
        }
    }
}

// ---------------------------------------------------------------------------
// Softmax in-place, vectorized: 1 float4 per thread (row = 512 = 128 x 4)
// ---------------------------------------------------------------------------
__global__ __launch_bounds__(128) void softmax_kernel(float* __restrict__ attn, int l)
{
    __shared__ float red[8];
    int row = blockIdx.x;
    int b = row >> 12;
    int rem = row & 4095;
    float4* p = reinterpret_cast<float4*>(
        attn + (size_t)b*(LL*HH*SS*SS) + (size_t)l*(HH*SS*SS) + (size_t)rem*SS);
    int t = threadIdx.x;
    int lane = t & 31, wid = t >> 5;

    float4 v = p[t];

    float mx = fmaxf(fmaxf(v.x, v.y), fmaxf(v.z, v.w));
#pragma unroll
    for (int o = 16; o > 0; o >>= 1) mx = fmaxf(mx, __shfl_xor_sync(0xffffffffu, mx, o));
    if (lane == 0) red[wid] = mx;
    __syncthreads();
    mx = fmaxf(fmaxf(red[0],red[1]), fmaxf(red[2],red[3]));

    v.x = __expf(v.x - mx); v.y = __expf(v.y - mx);
    v.z = __expf(v.z - mx); v.w = __expf(v.w - mx);
    float s = v.x + v.y + v.z + v.w;
#pragma unroll
    for (int o = 16; o > 0; o >>= 1) s += __shfl_xor_sync(0xffffffffu, s, o);
    if (lane == 0) red[4 + wid] = s;
    __syncthreads();
    s = red[4] + red[5] + red[6] + red[7];
    float inv = 1.0f / s;
    v.x *= inv; v.y *= inv; v.z *= inv; v.w *= inv;
    p[t] = v;
}

// ---------------------------------------------------------------------------
// LayerNorm: 2 rows per 256-thread block, float4 per thread.
// Writes fp32 out (+ optional tf32-rounded copy).
// ---------------------------------------------------------------------------
__global__ __launch_bounds__(256) void ln_kernel(
    const float* __restrict__ in,
    const float* __restrict__ g,
    const float* __restrict__ bta,
    float* __restrict__ outh,
    float* __restrict__ outhr)
{
    __shared__ float red[2][8];
    int half = threadIdx.x >> 7;           // 0 or 1
    int row  = blockIdx.x * 2 + half;
    int t    = threadIdx.x & 127;
    int lane = t & 31, wid = t >> 5;       // wid 0..3 within half

    const float4* p = reinterpret_cast<const float4*>(in + (size_t)row*DD);
    float4 v = p[t];

    float s  = v.x + v.y + v.z + v.w;
    float sq = v.x*v.x + v.y*v.y + v.z*v.z + v.w*v.w;
#pragma unroll
    for (int o = 16; o > 0; o >>= 1) {
        s  += __shfl_xor_sync(0xffffffffu, s,  o);
        sq += __shfl_xor_sync(0xffffffffu, sq, o);
    }
    if (lane == 0) { red[half][wid] = s; red[half][4+wid] = sq; }
    __syncthreads();
    s  = red[half][0]+red[half][1]+red[half][2]+red[half][3];
    sq = red[half][4]+red[half][5]+red[half][6]+red[half][7];
    float mu = s * (1.0f/DD);
    float var = sq * (1.0f/DD) - mu*mu;
    float rstd = rsqrtf(var + EPS);

    float4 gg = reinterpret_cast<const float4*>(g)[t];
    float4 bb = reinterpret_cast<const float4*>(bta)[t];
    float4 r;
    r.x = (v.x - mu) * rstd * gg.x + bb.x;
    r.y = (v.y - mu) * rstd * gg.y + bb.y;
    r.z = (v.z - mu) * rstd * gg.z + bb.z;
    r.w = (v.w - mu) * rstd * gg.w + bb.w;
    reinterpret_cast<float4*>(outh + (size_t)row*DD)[t] = r;
    if (outhr) {
        float4 rr; rr.x=tf32f(r.x); rr.y=tf32f(r.y); rr.z=tf32f(r.z); rr.w=tf32f(r.w);
        reinterpret_cast<float4*>(outhr + (size_t)row*DD)[t] = rr;
    }
}

// ---------------------------------------------------------------------------
extern "C" void kernel_launch(void* const* d_in, const int* in_sizes, int n_in,
                              void* d_out, int out_size)
{
    const int*   x    = (const int*)  d_in[0];
    const float* emb  = (const float*)d_in[1];
    const float* pe   = (const float*)d_in[2];
    const float* WQ   = (const float*)d_in[3];
    const float* bQ   = (const float*)d_in[4];
    const float* WK   = (const float*)d_in[5];
    const float* bK   = (const float*)d_in[6];
    const float* WV   = (const float*)d_in[7];
    const float* bV   = (const float*)d_in[8];
    const float* WO   = (const float*)d_in[9];
    const float* bO   = (const float*)d_in[10];
    const float* ln1g = (const float*)d_in[11];
    const float* ln1b = (const float*)d_in[12];
    const float* W1   = (const float*)d_in[13];
    const float* b1   = (const float*)d_in[14];
    const float* W2   = (const float*)d_in[15];
    const float* b2   = (const float*)d_in[16];
    const float* ln2g = (const float*)d_in[17];
    const float* ln2b = (const float*)d_in[18];

    float* out  = (float*)d_out;
    float* attn = out + (size_t)NTOK*DD;

    float *h, *hr, *q, *k, *v, *ctx, *tmp, *ff;
    cudaGetSymbolAddress((void**)&h,   g_h);
    cudaGetSymbolAddress((void**)&hr,  g_hr);
    cudaGetSymbolAddress((void**)&q,   g_q);
    cudaGetSymbolAddress((void**)&k,   g_k);
    cudaGetSymbolAddress((void**)&v,   g_v);
    cudaGetSymbolAddress((void**)&ctx, g_ctx);
    cudaGetSymbolAddress((void**)&tmp, g_tmp);
    cudaGetSymbolAddress((void**)&ff,  g_ff);

    // dynamic smem sizes (bytes)
    const int SM_D128 = (4*A_TILE_F + 4*B_TILE_F(128)) * 4;  // 75776
    const int SM_D64  = (4*A_TILE_F + 4*B_TILE_F(64))  * 4;  // 59392
    const int SM_SC   = (4*A_TILE_F + 4*A_TILE_F)      * 4;  // 81920

    static int attr_done = 0;
    if (!attr_done) {
        cudaFuncSetAttribute(gemm_tf32p<128,2>, cudaFuncAttributeMaxDynamicSharedMemorySize, SM_D128);
        cudaFuncSetAttribute(gemm_tf32p<64,4>,  cudaFuncAttributeMaxDynamicSharedMemorySize, SM_D64);
        cudaFuncSetAttribute(score_tf32p,       cudaFuncAttributeMaxDynamicSharedMemorySize, SM_SC);
        cudaFuncSetAttribute(ctx_tf32p,         cudaFuncAttributeMaxDynamicSharedMemorySize, SM_D64);
        attr_done = 1;
    }

    const float scale = 0.125f;

    embed_kernel<<<NTOK, 128>>>(x, emb, pe, h, hr);

    for (int l = 0; l < LL; l++) {
        const float* wq = WQ + (size_t)l*DD*DD;
        const float* wk = WK + (size_t)l*DD*DD;
        const float* wv = WV + (size_t)l*DD*DD;
        const float* wo = WO + (size_t)l*DD*DD;
        const float* w1 = W1 + (size_t)l*DD*DFF;
        const float* w2 = W2 + (size_t)l*DFF*DD;

        // fused QKV: A = hr (rounded), outputs rounded (feed score/ctx raw)
        gemm_tf32p<128,2><<<dim3(4,16,3), 256, SM_D128>>>(hr, DD,
            wq, wk, wv, DD,
            bQ + l*DD, bK + l*DD, bV + l*DD,
            nullptr,
            q, k, v, DD, DD, 0, 1);

        score_tf32p<<<dim3(4,4,32), 256, SM_SC>>>(q, k, x, attn, l, scale);
        softmax_kernel<<<BB*HH*SS, 128>>>(attn, l);
        ctx_tf32p<<<dim3(4,32), 256, SM_D64>>>(attn, v, ctx, l);

        // WO: A = ctx (rounded), residual = fp32 h, out fp32 (feeds LN only)
        gemm_tf32p<64,4><<<dim3(8,16,1), 256, SM_D64>>>(ctx, DD,
            wo, wo, wo, DD,
            bO + l*DD, bO + l*DD, bO + l*DD,
            h,
            tmp, tmp, tmp, DD, DD, 0, 0);
        ln_kernel<<<NTOK/2, 256>>>(tmp, ln1g + l*DD, ln1b + l*DD, h, hr);

        // FFN1: A = hr, output ff rounded (feeds FFN2 A raw)
        gemm_tf32p<128,2><<<dim3(16,16,1), 256, SM_D128>>>(hr, DD,
            w1, w1, w1, DFF,
            b1 + l*DFF, b1 + l*DFF, b1 + l*DFF,
            nullptr,
            ff, ff, ff, DFF, DD, 1, 1);

        // FFN2: A = ff (rounded), residual = fp32 h, out fp32
        gemm_tf32p<64,4><<<dim3(8,16,1), 256, SM_D64>>>(ff, DFF,
            w2, w2, w2, DD,
            b2 + l*DD, b2 + l*DD, b2 + l*DD,
            h,
            tmp, tmp, tmp, DD, DFF, 0, 0);

        if (l == LL-1) {
            ln_kernel<<<NTOK/2, 256>>>(tmp, ln2g + l*DD, ln2b + l*DD, out, nullptr);
        } else {
            ln_kernel<<<NTOK/2, 256>>>(tmp, ln2g + l*DD, ln2b + l*DD, h, hr);
        }
    }
}